// round 10
// baseline (speedup 1.0000x reference)
#include <cuda_runtime.h>
#include <cuda_bf16.h>
#include <stdint.h>
#include <math.h>

#define BB 4
#define TT 2048
#define DM 1024
#define NH 16
#define HD 64
#define MROWS (BB*TT)          // 8192
#define HALF_HD (HD/2)         // 32

// -------- scratch (no cudaMalloc allowed) --------
__device__ float g_q[MROWS*DM];
__device__ float g_k[MROWS*DM];
__device__ float g_v[MROWS*DM];
__device__ float g_cos[TT*HALF_HD];
__device__ float g_sin[TT*HALF_HD];

// bf16 split operands
__device__ __nv_bfloat16 g_xh[MROWS*DM];
__device__ __nv_bfloat16 g_xl[MROWS*DM];
__device__ __nv_bfloat16 g_aoh[MROWS*DM];
__device__ __nv_bfloat16 g_aol[MROWS*DM];
__device__ __nv_bfloat16 g_wh[4][DM*DM];
__device__ __nv_bfloat16 g_wl[4][DM*DM];
// attention operands (post-rope)
__device__ __nv_bfloat16 g_qh[MROWS*DM];
__device__ __nv_bfloat16 g_ql[MROWS*DM];
__device__ __nv_bfloat16 g_kh[MROWS*DM];
__device__ __nv_bfloat16 g_kl[MROWS*DM];
__device__ __nv_bfloat16 g_vh[MROWS*DM];
__device__ __nv_bfloat16 g_vl[MROWS*DM];

// ============================================================
// helpers
// ============================================================
__device__ __forceinline__ uint32_t smem_u32(const void* p) {
    uint32_t a;
    asm("{ .reg .u64 t; cvta.to.shared.u64 t, %1; cvt.u32.u64 %0, t; }"
        : "=r"(a) : "l"(p));
    return a;
}

__device__ __forceinline__ void ldm4(uint32_t r[4], uint32_t addr) {
    asm volatile("ldmatrix.sync.aligned.m8n8.x4.shared.b16 {%0,%1,%2,%3}, [%4];"
                 : "=r"(r[0]), "=r"(r[1]), "=r"(r[2]), "=r"(r[3]) : "r"(addr));
}
__device__ __forceinline__ void ldm4t(uint32_t r[4], uint32_t addr) {
    asm volatile("ldmatrix.sync.aligned.m8n8.x4.trans.shared.b16 {%0,%1,%2,%3}, [%4];"
                 : "=r"(r[0]), "=r"(r[1]), "=r"(r[2]), "=r"(r[3]) : "r"(addr));
}

__device__ __forceinline__ void mma16816(float c[4], const uint32_t a[4], const uint32_t b[2]) {
    asm volatile("mma.sync.aligned.m16n8k16.row.col.f32.bf16.bf16.f32 "
                 "{%0,%1,%2,%3}, {%4,%5,%6,%7}, {%8,%9}, {%0,%1,%2,%3};"
                 : "+f"(c[0]), "+f"(c[1]), "+f"(c[2]), "+f"(c[3])
                 : "r"(a[0]), "r"(a[1]), "r"(a[2]), "r"(a[3]), "r"(b[0]), "r"(b[1]));
}

__device__ __forceinline__ void cp16(uint32_t s, const void* g) {
    asm volatile("cp.async.cg.shared.global [%0], [%1], 16;" :: "r"(s), "l"(g));
}

// 32-col (64B row) tile swizzle — gemm tiles (proven)
__device__ __forceinline__ uint32_t swz_off(int row, int chunk) {
    return (uint32_t)(row * 64 + ((chunk ^ (row & 3) ^ ((row >> 2) & 3)) << 4));
}
// 64-col (128B row) tile swizzle — attention tiles (proven)
__device__ __forceinline__ uint32_t swz64(int row, int chunk) {
    return (uint32_t)(row * 128 + (((chunk ^ (row & 7)) & 7) << 4));
}

__device__ __forceinline__ void tile_cp(uint32_t sbase, const __nv_bfloat16* __restrict__ src,
                                        int row0, int K, int kc, int tid) {
#pragma unroll
    for (int it = 0; it < 2; ++it) {
        int idx = tid + it * 256;
        int r = idx >> 2, c = idx & 3;
        uint32_t soff = sbase + swz_off(r, c);
        const void* g = src + (size_t)(row0 + r) * K + kc + c * 8;
        cp16(soff, g);
    }
}

// pack two fp32 -> bf16x2 hi and residual-lo regs
__device__ __forceinline__ void splitpack(float p0, float p1, uint32_t& h, uint32_t& l) {
    __nv_bfloat16 h0 = __float2bfloat16(p0);
    __nv_bfloat16 h1 = __float2bfloat16(p1);
    __nv_bfloat16 l0 = __float2bfloat16(p0 - __bfloat162float(h0));
    __nv_bfloat16 l1 = __float2bfloat16(p1 - __bfloat162float(h1));
    __nv_bfloat162 hh(h0, h1), ll(l0, l1);
    h = *reinterpret_cast<uint32_t*>(&hh);
    l = *reinterpret_cast<uint32_t*>(&ll);
}

// ============================================================
// fp32 -> bf16 hi/lo split
// ============================================================
__global__ void split_kernel(const float* __restrict__ src,
                             __nv_bfloat16* __restrict__ hi,
                             __nv_bfloat16* __restrict__ lo, int n4) {
    int i = blockIdx.x * blockDim.x + threadIdx.x;
    if (i >= n4) return;
    float4 x = reinterpret_cast<const float4*>(src)[i];
    __nv_bfloat16 h0 = __float2bfloat16(x.x);
    __nv_bfloat16 h1 = __float2bfloat16(x.y);
    __nv_bfloat16 h2 = __float2bfloat16(x.z);
    __nv_bfloat16 h3 = __float2bfloat16(x.w);
    __nv_bfloat16 l0 = __float2bfloat16(x.x - __bfloat162float(h0));
    __nv_bfloat16 l1 = __float2bfloat16(x.y - __bfloat162float(h1));
    __nv_bfloat16 l2 = __float2bfloat16(x.z - __bfloat162float(h2));
    __nv_bfloat16 l3 = __float2bfloat16(x.w - __bfloat162float(h3));
    __nv_bfloat162* hp = reinterpret_cast<__nv_bfloat162*>(hi);
    __nv_bfloat162* lp = reinterpret_cast<__nv_bfloat162*>(lo);
    hp[2*i]   = __nv_bfloat162(h0, h1);
    hp[2*i+1] = __nv_bfloat162(h2, h3);
    lp[2*i]   = __nv_bfloat162(l0, l1);
    lp[2*i+1] = __nv_bfloat162(l2, l3);
}

// ============================================================
// GEMM mainloop core (128x128 tile, bf16x3, double-buffered)
// ============================================================
#define GM_SMEM 65536

__device__ __forceinline__ void gemm_core(
    uint32_t sb, const __nv_bfloat16* Ah, const __nv_bfloat16* Al,
    const __nv_bfloat16* Bh, const __nv_bfloat16* Bl,
    int m0, int n0, int K, int tid, int lane,
    int wm, int wn, float acc[4][4][4])
{
    const int nch = K / 32;

    tile_cp(sb +     0, Ah, m0, K, 0, tid);
    tile_cp(sb +  8192, Al, m0, K, 0, tid);
    tile_cp(sb + 16384, Bh, n0, K, 0, tid);
    tile_cp(sb + 24576, Bl, n0, K, 0, tid);
    asm volatile("cp.async.commit_group;");

    for (int ch = 0; ch < nch; ++ch) {
        if (ch + 1 < nch) {
            uint32_t nb = sb + (uint32_t)(((ch + 1) & 1) * 32768);
            int kc = (ch + 1) * 32;
            tile_cp(nb +     0, Ah, m0, K, kc, tid);
            tile_cp(nb +  8192, Al, m0, K, kc, tid);
            tile_cp(nb + 16384, Bh, n0, K, kc, tid);
            tile_cp(nb + 24576, Bl, n0, K, kc, tid);
            asm volatile("cp.async.commit_group;");
            asm volatile("cp.async.wait_group 1;");
        } else {
            asm volatile("cp.async.wait_group 0;");
        }
        __syncthreads();

        uint32_t bufA_h = sb + (uint32_t)((ch & 1) * 32768);
        uint32_t bufA_l = bufA_h + 8192;
        uint32_t bufB_h = bufA_h + 16384;
        uint32_t bufB_l = bufA_h + 24576;

#pragma unroll
        for (int ks = 0; ks < 2; ++ks) {
            uint32_t ah[4][4], al[4][4], bh[4][2], bl[4][2];

            int ra  = ((lane >> 3) & 1) * 8 + (lane & 7);
            int caf = (lane >> 4) & 1;
#pragma unroll
            for (int mt = 0; mt < 4; ++mt) {
                int row = wm + mt * 16 + ra;
                uint32_t off = swz_off(row, ks * 2 + caf);
                ldm4(ah[mt], bufA_h + off);
                ldm4(al[mt], bufA_l + off);
            }

            int rb  = ((lane >> 4) & 1) * 8 + (lane & 7);
            int cbf = (lane >> 3) & 1;
#pragma unroll
            for (int p = 0; p < 2; ++p) {
                int row = wn + p * 16 + rb;
                uint32_t off = swz_off(row, ks * 2 + cbf);
                uint32_t t[4];
                ldm4(t, bufB_h + off);
                bh[p*2][0] = t[0]; bh[p*2][1] = t[1];
                bh[p*2+1][0] = t[2]; bh[p*2+1][1] = t[3];
                ldm4(t, bufB_l + off);
                bl[p*2][0] = t[0]; bl[p*2][1] = t[1];
                bl[p*2+1][0] = t[2]; bl[p*2+1][1] = t[3];
            }

#pragma unroll
            for (int mt = 0; mt < 4; ++mt)
#pragma unroll
                for (int nt = 0; nt < 4; ++nt) {
                    mma16816(acc[mt][nt], ah[mt], bh[nt]);
                    mma16816(acc[mt][nt], ah[mt], bl[nt]);
                    mma16816(acc[mt][nt], al[mt], bh[nt]);
                }
        }
        __syncthreads();
    }
}

// ============================================================
// Fused QKV GEMM: blockIdx.z selects Wq/Wk/Wv; fp32 outputs
// (identical epilogue to round-8 gemm_mma)
// ============================================================
__global__ void __launch_bounds__(256) gemm_qkv(
    const __nv_bfloat16* __restrict__ xh, const __nv_bfloat16* __restrict__ xl,
    const __nv_bfloat16* __restrict__ wh, const __nv_bfloat16* __restrict__ wl,
    float* __restrict__ q, float* __restrict__ k, float* __restrict__ v)
{
    extern __shared__ char smem[];
    uint32_t sb = smem_u32(smem);
    int tid = threadIdx.x, lane = tid & 31, wid = tid >> 5;
    int m0 = blockIdx.y * 128, n0 = blockIdx.x * 128;
    int wm = (wid & 1) * 64, wn = (wid >> 1) * 32;
    int z = blockIdx.z;

    const __nv_bfloat16* Bh = wh + (size_t)z * DM * DM;
    const __nv_bfloat16* Bl = wl + (size_t)z * DM * DM;
    float* C = (z == 0) ? q : (z == 1) ? k : v;

    float acc[4][4][4];
#pragma unroll
    for (int a = 0; a < 4; a++)
#pragma unroll
        for (int b = 0; b < 4; b++)
#pragma unroll
            for (int c = 0; c < 4; c++) acc[a][b][c] = 0.0f;

    gemm_core(sb, xh, xl, Bh, Bl, m0, n0, DM, tid, lane, wm, wn, acc);

    int g = lane >> 2, c2 = (lane & 3) * 2;
#pragma unroll
    for (int mt = 0; mt < 4; ++mt)
#pragma unroll
        for (int nt = 0; nt < 4; ++nt) {
            int row = m0 + wm + mt * 16 + g;
            int col = n0 + wn + nt * 8 + c2;
            *reinterpret_cast<float2*>(C + (size_t)row * DM + col) =
                make_float2(acc[mt][nt][0], acc[mt][nt][1]);
            *reinterpret_cast<float2*>(C + (size_t)(row + 8) * DM + col) =
                make_float2(acc[mt][nt][2], acc[mt][nt][3]);
        }
}

// ============================================================
// Generic GEMM (fp32 out) — used for the Wo projection
// ============================================================
__global__ void __launch_bounds__(256) gemm_mma(
    const __nv_bfloat16* __restrict__ Ah, const __nv_bfloat16* __restrict__ Al,
    const __nv_bfloat16* __restrict__ Bh, const __nv_bfloat16* __restrict__ Bl,
    float* __restrict__ C, int M, int N, int K)
{
    extern __shared__ char smem[];
    uint32_t sb = smem_u32(smem);
    int tid = threadIdx.x, lane = tid & 31, wid = tid >> 5;
    int m0 = blockIdx.y * 128, n0 = blockIdx.x * 128;
    int wm = (wid & 1) * 64, wn = (wid >> 1) * 32;

    float acc[4][4][4];
#pragma unroll
    for (int a = 0; a < 4; a++)
#pragma unroll
        for (int b = 0; b < 4; b++)
#pragma unroll
            for (int c = 0; c < 4; c++) acc[a][b][c] = 0.0f;

    gemm_core(sb, Ah, Al, Bh, Bl, m0, n0, K, tid, lane, wm, wn, acc);

    int g = lane >> 2, c2 = (lane & 3) * 2;
#pragma unroll
    for (int mt = 0; mt < 4; ++mt)
#pragma unroll
        for (int nt = 0; nt < 4; ++nt) {
            int row = m0 + wm + mt * 16 + g;
            int col = n0 + wn + nt * 8 + c2;
            *reinterpret_cast<float2*>(C + (size_t)row * N + col) =
                make_float2(acc[mt][nt][0], acc[mt][nt][1]);
            *reinterpret_cast<float2*>(C + (size_t)(row + 8) * N + col) =
                make_float2(acc[mt][nt][2], acc[mt][nt][3]);
        }
}

// ============================================================
// RoPE sin/cos table (fp64)
// ============================================================
__global__ void rope_table_kernel() {
    int i = blockIdx.x * blockDim.x + threadIdx.x;
    if (i >= TT * HALF_HD) return;
    int t = i / HALF_HD;
    int f = i % HALF_HD;
    double inv = exp(-((double)f / (double)HALF_HD) * log(10000.0));
    double ang = (double)t * inv;
    g_cos[i] = (float)cos(ang);
    g_sin[i] = (float)sin(ang);
}

// ============================================================
// RoPE + bf16 hi/lo split for Q,K (fused; fp32 in, bf16 out)
// ============================================================
__global__ void rope_split_kernel(const float* __restrict__ q, const float* __restrict__ k,
                                  __nv_bfloat16* __restrict__ qh, __nv_bfloat16* __restrict__ ql,
                                  __nv_bfloat16* __restrict__ kh, __nv_bfloat16* __restrict__ kl) {
    int i = blockIdx.x * blockDim.x + threadIdx.x;
    if (i >= BB * TT * NH * HALF_HD) return;
    int f    = i & (HALF_HD - 1);
    int rest = i >> 5;
    int h    = rest & (NH - 1);
    int bt   = rest >> 4;
    int t    = bt & (TT - 1);
    int off  = bt * DM + h * HD + f;
    float c = g_cos[t * HALF_HD + f];
    float s = g_sin[t * HALF_HD + f];

    float q1 = q[off], q2 = q[off + HALF_HD];
    float qa = q1 * c - q2 * s;
    float qb = q2 * c + q1 * s;
    __nv_bfloat16 ha = __float2bfloat16(qa);
    __nv_bfloat16 hb = __float2bfloat16(qb);
    qh[off] = ha;  qh[off + HALF_HD] = hb;
    ql[off] = __float2bfloat16(qa - __bfloat162float(ha));
    ql[off + HALF_HD] = __float2bfloat16(qb - __bfloat162float(hb));

    float k1 = k[off], k2 = k[off + HALF_HD];
    float ka = k1 * c - k2 * s;
    float kb = k2 * c + k1 * s;
    ha = __float2bfloat16(ka);
    hb = __float2bfloat16(kb);
    kh[off] = ha;  kh[off + HALF_HD] = hb;
    kl[off] = __float2bfloat16(ka - __bfloat162float(ha));
    kl[off + HALF_HD] = __float2bfloat16(kb - __bfloat162float(hb));
}

// ============================================================
// Tensor-core flash attention (causal, FA2-style, bf16x3)
// fp32 output (round-8 proven)
// ============================================================
#define FA_SMEM 98304
#define FQH 0
#define FQL 16384
#define FKH 0
#define FKL 8192
#define FVH 16384
#define FVL 24576

__global__ void __launch_bounds__(256) flash_mma(
    const __nv_bfloat16* __restrict__ qh, const __nv_bfloat16* __restrict__ ql,
    const __nv_bfloat16* __restrict__ kh, const __nv_bfloat16* __restrict__ kl,
    const __nv_bfloat16* __restrict__ vh, const __nv_bfloat16* __restrict__ vl,
    float* __restrict__ O)
{
    extern __shared__ char smem[];
    uint32_t sb = smem_u32(smem);
    int tid = threadIdx.x, lane = tid & 31, w = tid >> 5;

    int qt = (int)gridDim.x - 1 - (int)blockIdx.x;
    int bh_ = blockIdx.y;
    int b = bh_ >> 4, h = bh_ & 15;
    size_t base = (size_t)b * TT * DM + h * HD;
    int q0 = qt * 128;

    const __nv_bfloat16* Qh = qh + base;
    const __nv_bfloat16* Ql = ql + base;
    const __nv_bfloat16* Kh = kh + base;
    const __nv_bfloat16* Kl = kl + base;
    const __nv_bfloat16* Vh = vh + base;
    const __nv_bfloat16* Vl = vl + base;

    for (int i = tid; i < 1024; i += 256) {
        int r = i >> 3, c = i & 7;
        size_t g = (size_t)(q0 + r) * DM + c * 8;
        cp16(sb + FQH + swz64(r, c), Qh + g);
        cp16(sb + FQL + swz64(r, c), Ql + g);
    }
    {
        uint32_t buf = sb + 32768;
        for (int i = tid; i < 512; i += 256) {
            int r = i >> 3, c = i & 7;
            size_t g = (size_t)r * DM + c * 8;
            uint32_t so = swz64(r, c);
            cp16(buf + FKH + so, Kh + g);
            cp16(buf + FKL + so, Kl + g);
            cp16(buf + FVH + so, Vh + g);
            cp16(buf + FVL + so, Vl + g);
        }
    }
    asm volatile("cp.async.commit_group;");

    const float NEG_INF = -__int_as_float(0x7f800000);
    float m0 = NEG_INF, m1 = NEG_INF, l0 = 0.0f, l1 = 0.0f;
    float o[8][4];
#pragma unroll
    for (int nt = 0; nt < 8; nt++)
#pragma unroll
        for (int c = 0; c < 4; c++) o[nt][c] = 0.0f;

    int nkt = 2 * qt + 2;
    int row0 = q0 + w * 16 + (lane >> 2);

    for (int kt = 0; kt < nkt; kt++) {
        uint32_t cur = sb + 32768u + (uint32_t)((kt & 1) * 32768);
        if (kt + 1 < nkt) {
            __syncthreads();
            uint32_t nb = sb + 32768u + (uint32_t)(((kt + 1) & 1) * 32768);
            int k0n = (kt + 1) * 64;
            for (int i = tid; i < 512; i += 256) {
                int r = i >> 3, c = i & 7;
                size_t g = (size_t)(k0n + r) * DM + c * 8;
                uint32_t so = swz64(r, c);
                cp16(nb + FKH + so, Kh + g);
                cp16(nb + FKL + so, Kl + g);
                cp16(nb + FVH + so, Vh + g);
                cp16(nb + FVL + so, Vl + g);
            }
            asm volatile("cp.async.commit_group;");
            asm volatile("cp.async.wait_group 1;");
        } else {
            asm volatile("cp.async.wait_group 0;");
        }
        __syncthreads();

        int k0 = kt * 64;

        float s[8][4];
#pragma unroll
        for (int nt = 0; nt < 8; nt++)
#pragma unroll
            for (int c = 0; c < 4; c++) s[nt][c] = 0.0f;

        int ra  = ((lane >> 3) & 1) * 8 + (lane & 7);
        int caf = (lane >> 4) & 1;
        int rb  = ((lane >> 4) & 1) * 8 + (lane & 7);
        int cbf = (lane >> 3) & 1;

#pragma unroll
        for (int ks = 0; ks < 4; ++ks) {
            uint32_t aH[4], aL[4];
            uint32_t qoff = swz64(w * 16 + ra, ks * 2 + caf);
            ldm4(aH, sb + FQH + qoff);
            ldm4(aL, sb + FQL + qoff);

            uint32_t bH[8][2], bL[8][2];
#pragma unroll
            for (int p = 0; p < 4; ++p) {
                uint32_t off = swz64(p * 16 + rb, ks * 2 + cbf);
                uint32_t t[4];
                ldm4(t, cur + FKH + off);
                bH[p*2][0] = t[0]; bH[p*2][1] = t[1];
                bH[p*2+1][0] = t[2]; bH[p*2+1][1] = t[3];
                ldm4(t, cur + FKL + off);
                bL[p*2][0] = t[0]; bL[p*2][1] = t[1];
                bL[p*2+1][0] = t[2]; bL[p*2+1][1] = t[3];
            }
#pragma unroll
            for (int nt = 0; nt < 8; ++nt) {
                mma16816(s[nt], aH, bH[nt]);
                mma16816(s[nt], aH, bL[nt]);
                mma16816(s[nt], aL, bH[nt]);
            }
        }

        bool needmask = (k0 + 63 > q0);
#pragma unroll
        for (int nt = 0; nt < 8; ++nt) {
#pragma unroll
            for (int c = 0; c < 4; ++c) {
                float v = s[nt][c] * 0.125f;
                if (needmask) {
                    int col = k0 + nt * 8 + (lane & 3) * 2 + (c & 1);
                    int rowg = row0 + ((c >> 1) << 3);
                    if (col > rowg) v = NEG_INF;
                }
                s[nt][c] = v;
            }
        }

        float mx0 = NEG_INF, mx1 = NEG_INF;
#pragma unroll
        for (int nt = 0; nt < 8; ++nt) {
            mx0 = fmaxf(mx0, fmaxf(s[nt][0], s[nt][1]));
            mx1 = fmaxf(mx1, fmaxf(s[nt][2], s[nt][3]));
        }
        mx0 = fmaxf(mx0, __shfl_xor_sync(0xffffffffu, mx0, 1));
        mx0 = fmaxf(mx0, __shfl_xor_sync(0xffffffffu, mx0, 2));
        mx1 = fmaxf(mx1, __shfl_xor_sync(0xffffffffu, mx1, 1));
        mx1 = fmaxf(mx1, __shfl_xor_sync(0xffffffffu, mx1, 2));

        float mn0 = fmaxf(m0, mx0), mn1 = fmaxf(m1, mx1);
        float al0 = __expf(m0 - mn0), al1 = __expf(m1 - mn1);
        if (m0 == NEG_INF && mn0 == NEG_INF) al0 = 1.0f;
        if (m1 == NEG_INF && mn1 == NEG_INF) al1 = 1.0f;
        m0 = mn0; m1 = mn1;

        float ls0 = 0.0f, ls1 = 0.0f;
#pragma unroll
        for (int nt = 0; nt < 8; ++nt) {
            float p0 = (s[nt][0] == NEG_INF) ? 0.0f : __expf(s[nt][0] - mn0);
            float p1 = (s[nt][1] == NEG_INF) ? 0.0f : __expf(s[nt][1] - mn0);
            float p2 = (s[nt][2] == NEG_INF) ? 0.0f : __expf(s[nt][2] - mn1);
            float p3 = (s[nt][3] == NEG_INF) ? 0.0f : __expf(s[nt][3] - mn1);
            s[nt][0] = p0; s[nt][1] = p1; s[nt][2] = p2; s[nt][3] = p3;
            ls0 += p0 + p1; ls1 += p2 + p3;
        }
        ls0 += __shfl_xor_sync(0xffffffffu, ls0, 1);
        ls0 += __shfl_xor_sync(0xffffffffu, ls0, 2);
        ls1 += __shfl_xor_sync(0xffffffffu, ls1, 1);
        ls1 += __shfl_xor_sync(0xffffffffu, ls1, 2);
        l0 = l0 * al0 + ls0;
        l1 = l1 * al1 + ls1;

#pragma unroll
        for (int nt = 0; nt < 8; ++nt) {
            o[nt][0] *= al0; o[nt][1] *= al0;
            o[nt][2] *= al1; o[nt][3] *= al1;
        }

#pragma unroll
        for (int ks = 0; ks < 4; ++ks) {
            uint32_t pH[4], pL[4];
            splitpack(s[2*ks][0],   s[2*ks][1],   pH[0], pL[0]);
            splitpack(s[2*ks][2],   s[2*ks][3],   pH[1], pL[1]);
            splitpack(s[2*ks+1][0], s[2*ks+1][1], pH[2], pL[2]);
            splitpack(s[2*ks+1][2], s[2*ks+1][3], pH[3], pL[3]);

            int mm = lane >> 3, la = lane & 7;
            int vrow = ks * 16 + (mm & 1) * 8 + la;
#pragma unroll
            for (int ntp = 0; ntp < 4; ++ntp) {
                int vchunk = ntp * 2 + (mm >> 1);
                uint32_t off = swz64(vrow, vchunk);
                uint32_t tH[4], tL[4];
                ldm4t(tH, cur + FVH + off);
                ldm4t(tL, cur + FVL + off);
                uint32_t b0H[2] = {tH[0], tH[1]}, b1H[2] = {tH[2], tH[3]};
                uint32_t b0L[2] = {tL[0], tL[1]}, b1L[2] = {tL[2], tL[3]};
                mma16816(o[2*ntp],   pH, b0H);
                mma16816(o[2*ntp],   pH, b0L);
                mma16816(o[2*ntp],   pL, b0H);
                mma16816(o[2*ntp+1], pH, b1H);
                mma16816(o[2*ntp+1], pH, b1L);
                mma16816(o[2*ntp+1], pL, b1H);
            }
        }
    }

    float inv0 = 1.0f / l0, inv1 = 1.0f / l1;
    float* Op = O + base;
    int c2 = (lane & 3) * 2;
#pragma unroll
    for (int nt = 0; nt < 8; ++nt) {
        *reinterpret_cast<float2*>(Op + (size_t)row0 * DM + nt * 8 + c2) =
            make_float2(o[nt][0] * inv0, o[nt][1] * inv0);
        *reinterpret_cast<float2*>(Op + (size_t)(row0 + 8) * DM + nt * 8 + c2) =
            make_float2(o[nt][2] * inv1, o[nt][3] * inv1);
    }
}

// ============================================================
// launch
// ============================================================
extern "C" void kernel_launch(void* const* d_in, const int* in_sizes, int n_in,
                              void* d_out, int out_size) {
    const float* x  = (const float*)d_in[0];
    const float* Wq = (const float*)d_in[1];
    const float* Wk = (const float*)d_in[2];
    const float* Wv = (const float*)d_in[3];
    const float* Wo = (const float*)d_in[4];
    float* out = (float*)d_out;

    float *q, *k, *v;
    cudaGetSymbolAddress((void**)&q,  g_q);
    cudaGetSymbolAddress((void**)&k,  g_k);
    cudaGetSymbolAddress((void**)&v,  g_v);

    __nv_bfloat16 *xh, *xl, *aoh, *aol, *wh, *wl;
    __nv_bfloat16 *qh, *ql, *kh, *kl, *vh, *vl;
    cudaGetSymbolAddress((void**)&xh,  g_xh);
    cudaGetSymbolAddress((void**)&xl,  g_xl);
    cudaGetSymbolAddress((void**)&aoh, g_aoh);
    cudaGetSymbolAddress((void**)&aol, g_aol);
    cudaGetSymbolAddress((void**)&wh,  g_wh);
    cudaGetSymbolAddress((void**)&wl,  g_wl);
    cudaGetSymbolAddress((void**)&qh,  g_qh);
    cudaGetSymbolAddress((void**)&ql,  g_ql);
    cudaGetSymbolAddress((void**)&kh,  g_kh);
    cudaGetSymbolAddress((void**)&kl,  g_kl);
    cudaGetSymbolAddress((void**)&vh,  g_vh);
    cudaGetSymbolAddress((void**)&vl,  g_vl);

    cudaFuncSetAttribute(gemm_qkv,  cudaFuncAttributeMaxDynamicSharedMemorySize, GM_SMEM);
    cudaFuncSetAttribute(gemm_mma,  cudaFuncAttributeMaxDynamicSharedMemorySize, GM_SMEM);
    cudaFuncSetAttribute(flash_mma, cudaFuncAttributeMaxDynamicSharedMemorySize, FA_SMEM);

    rope_table_kernel<<<(TT * HALF_HD + 255) / 256, 256>>>();

    int nx4 = MROWS * DM / 4;
    int nw4 = DM * DM / 4;
    split_kernel<<<(nx4 + 255) / 256, 256>>>(x, xh, xl, nx4);
    split_kernel<<<(nw4 + 255) / 256, 256>>>(Wq, wh + 0 * (size_t)DM * DM, wl + 0 * (size_t)DM * DM, nw4);
    split_kernel<<<(nw4 + 255) / 256, 256>>>(Wk, wh + 1 * (size_t)DM * DM, wl + 1 * (size_t)DM * DM, nw4);
    split_kernel<<<(nw4 + 255) / 256, 256>>>(Wv, wh + 2 * (size_t)DM * DM, wl + 2 * (size_t)DM * DM, nw4);
    split_kernel<<<(nw4 + 255) / 256, 256>>>(Wo, wh + 3 * (size_t)DM * DM, wl + 3 * (size_t)DM * DM, nw4);

    // fused QKV projections — ONE launch, fp32 outputs (round-8 epilogue)
    gemm_qkv<<<dim3(DM / 128, MROWS / 128, 3), 256, GM_SMEM>>>(
        xh, xl, wh, wl, q, k, v);

    rope_split_kernel<<<(BB * TT * NH * HALF_HD + 255) / 256, 256>>>(q, k, qh, ql, kh, kl);
    split_kernel<<<(nx4 + 255) / 256, 256>>>(v, vh, vl, nx4);

    flash_mma<<<dim3(TT / 128, BB * NH), 256, FA_SMEM>>>(qh, ql, kh, kl, vh, vl, (float*)g_q);

    // reuse g_q as fp32 attention output buffer, then split for Wo GEMM
    split_kernel<<<(nx4 + 255) / 256, 256>>>((const float*)g_q, aoh, aol, nx4);
    gemm_mma<<<dim3(DM / 128, MROWS / 128), 256, GM_SMEM>>>(
        aoh, aol, wh + 3 * (size_t)DM * DM, wl + 3 * (size_t)DM * DM, out, MROWS, DM, DM);
}

// round 11
// speedup vs baseline: 1.4953x; 1.4953x over previous
#include <cuda_runtime.h>
#include <cuda_bf16.h>
#include <stdint.h>
#include <math.h>

#define BB 4
#define TT 2048
#define DM 1024
#define NH 16
#define HD 64
#define MROWS (BB*TT)          // 8192
#define HALF_HD (HD/2)         // 32

// -------- scratch (no cudaMalloc allowed) --------
__device__ float g_q[MROWS*DM];
__device__ float g_k[MROWS*DM];
__device__ float g_v[MROWS*DM];
__device__ float g_cos[TT*HALF_HD];
__device__ float g_sin[TT*HALF_HD];

// bf16 split operands
__device__ __nv_bfloat16 g_xh[MROWS*DM];
__device__ __nv_bfloat16 g_xl[MROWS*DM];
__device__ __nv_bfloat16 g_aoh[MROWS*DM];
__device__ __nv_bfloat16 g_aol[MROWS*DM];
__device__ __nv_bfloat16 g_wh[4][DM*DM];
__device__ __nv_bfloat16 g_wl[4][DM*DM];
// attention operands (post-rope)
__device__ __nv_bfloat16 g_qh[MROWS*DM];
__device__ __nv_bfloat16 g_ql[MROWS*DM];
__device__ __nv_bfloat16 g_kh[MROWS*DM];
__device__ __nv_bfloat16 g_kl[MROWS*DM];
__device__ __nv_bfloat16 g_vh[MROWS*DM];
__device__ __nv_bfloat16 g_vl[MROWS*DM];

// ============================================================
// helpers
// ============================================================
__device__ __forceinline__ uint32_t smem_u32(const void* p) {
    uint32_t a;
    asm("{ .reg .u64 t; cvta.to.shared.u64 t, %1; cvt.u32.u64 %0, t; }"
        : "=r"(a) : "l"(p));
    return a;
}

__device__ __forceinline__ void ldm4(uint32_t r[4], uint32_t addr) {
    asm volatile("ldmatrix.sync.aligned.m8n8.x4.shared.b16 {%0,%1,%2,%3}, [%4];"
                 : "=r"(r[0]), "=r"(r[1]), "=r"(r[2]), "=r"(r[3]) : "r"(addr));
}
__device__ __forceinline__ void ldm4t(uint32_t r[4], uint32_t addr) {
    asm volatile("ldmatrix.sync.aligned.m8n8.x4.trans.shared.b16 {%0,%1,%2,%3}, [%4];"
                 : "=r"(r[0]), "=r"(r[1]), "=r"(r[2]), "=r"(r[3]) : "r"(addr));
}

__device__ __forceinline__ void mma16816(float c[4], const uint32_t a[4], const uint32_t b[2]) {
    asm volatile("mma.sync.aligned.m16n8k16.row.col.f32.bf16.bf16.f32 "
                 "{%0,%1,%2,%3}, {%4,%5,%6,%7}, {%8,%9}, {%0,%1,%2,%3};"
                 : "+f"(c[0]), "+f"(c[1]), "+f"(c[2]), "+f"(c[3])
                 : "r"(a[0]), "r"(a[1]), "r"(a[2]), "r"(a[3]), "r"(b[0]), "r"(b[1]));
}

__device__ __forceinline__ void cp16(uint32_t s, const void* g) {
    asm volatile("cp.async.cg.shared.global [%0], [%1], 16;" :: "r"(s), "l"(g));
}

// 32-col (64B row) tile swizzle — gemm tiles (proven)
__device__ __forceinline__ uint32_t swz_off(int row, int chunk) {
    return (uint32_t)(row * 64 + ((chunk ^ (row & 3) ^ ((row >> 2) & 3)) << 4));
}
// 64-col (128B row) tile swizzle — attention tiles (proven)
__device__ __forceinline__ uint32_t swz64(int row, int chunk) {
    return (uint32_t)(row * 128 + (((chunk ^ (row & 7)) & 7) << 4));
}

__device__ __forceinline__ void tile_cp(uint32_t sbase, const __nv_bfloat16* __restrict__ src,
                                        int row0, int K, int kc, int tid) {
#pragma unroll
    for (int it = 0; it < 2; ++it) {
        int idx = tid + it * 256;
        int r = idx >> 2, c = idx & 3;
        uint32_t soff = sbase + swz_off(r, c);
        const void* g = src + (size_t)(row0 + r) * K + kc + c * 8;
        cp16(soff, g);
    }
}

// pack two fp32 -> bf16x2 hi and residual-lo regs
__device__ __forceinline__ void splitpack(float p0, float p1, uint32_t& h, uint32_t& l) {
    __nv_bfloat16 h0 = __float2bfloat16(p0);
    __nv_bfloat16 h1 = __float2bfloat16(p1);
    __nv_bfloat16 l0 = __float2bfloat16(p0 - __bfloat162float(h0));
    __nv_bfloat16 l1 = __float2bfloat16(p1 - __bfloat162float(h1));
    __nv_bfloat162 hh(h0, h1), ll(l0, l1);
    h = *reinterpret_cast<uint32_t*>(&hh);
    l = *reinterpret_cast<uint32_t*>(&ll);
}

// ============================================================
// fp32 -> bf16 hi/lo split
// ============================================================
__global__ void split_kernel(const float* __restrict__ src,
                             __nv_bfloat16* __restrict__ hi,
                             __nv_bfloat16* __restrict__ lo, int n4) {
    int i = blockIdx.x * blockDim.x + threadIdx.x;
    if (i >= n4) return;
    float4 x = reinterpret_cast<const float4*>(src)[i];
    __nv_bfloat16 h0 = __float2bfloat16(x.x);
    __nv_bfloat16 h1 = __float2bfloat16(x.y);
    __nv_bfloat16 h2 = __float2bfloat16(x.z);
    __nv_bfloat16 h3 = __float2bfloat16(x.w);
    __nv_bfloat16 l0 = __float2bfloat16(x.x - __bfloat162float(h0));
    __nv_bfloat16 l1 = __float2bfloat16(x.y - __bfloat162float(h1));
    __nv_bfloat16 l2 = __float2bfloat16(x.z - __bfloat162float(h2));
    __nv_bfloat16 l3 = __float2bfloat16(x.w - __bfloat162float(h3));
    __nv_bfloat162* hp = reinterpret_cast<__nv_bfloat162*>(hi);
    __nv_bfloat162* lp = reinterpret_cast<__nv_bfloat162*>(lo);
    hp[2*i]   = __nv_bfloat162(h0, h1);
    hp[2*i+1] = __nv_bfloat162(h2, h3);
    lp[2*i]   = __nv_bfloat162(l0, l1);
    lp[2*i+1] = __nv_bfloat162(l2, l3);
}

// ============================================================
// GEMM mainloop core (128x128 tile, bf16x3, double-buffered)
// ============================================================
#define GM_SMEM 65536

__device__ __forceinline__ void gemm_core(
    uint32_t sb, const __nv_bfloat16* Ah, const __nv_bfloat16* Al,
    const __nv_bfloat16* Bh, const __nv_bfloat16* Bl,
    int m0, int n0, int K, int tid, int lane,
    int wm, int wn, float acc[4][4][4])
{
    const int nch = K / 32;

    tile_cp(sb +     0, Ah, m0, K, 0, tid);
    tile_cp(sb +  8192, Al, m0, K, 0, tid);
    tile_cp(sb + 16384, Bh, n0, K, 0, tid);
    tile_cp(sb + 24576, Bl, n0, K, 0, tid);
    asm volatile("cp.async.commit_group;");

    for (int ch = 0; ch < nch; ++ch) {
        if (ch + 1 < nch) {
            uint32_t nb = sb + (uint32_t)(((ch + 1) & 1) * 32768);
            int kc = (ch + 1) * 32;
            tile_cp(nb +     0, Ah, m0, K, kc, tid);
            tile_cp(nb +  8192, Al, m0, K, kc, tid);
            tile_cp(nb + 16384, Bh, n0, K, kc, tid);
            tile_cp(nb + 24576, Bl, n0, K, kc, tid);
            asm volatile("cp.async.commit_group;");
            asm volatile("cp.async.wait_group 1;");
        } else {
            asm volatile("cp.async.wait_group 0;");
        }
        __syncthreads();

        uint32_t bufA_h = sb + (uint32_t)((ch & 1) * 32768);
        uint32_t bufA_l = bufA_h + 8192;
        uint32_t bufB_h = bufA_h + 16384;
        uint32_t bufB_l = bufA_h + 24576;

#pragma unroll
        for (int ks = 0; ks < 2; ++ks) {
            uint32_t ah[4][4], al[4][4], bh[4][2], bl[4][2];

            int ra  = ((lane >> 3) & 1) * 8 + (lane & 7);
            int caf = (lane >> 4) & 1;
#pragma unroll
            for (int mt = 0; mt < 4; ++mt) {
                int row = wm + mt * 16 + ra;
                uint32_t off = swz_off(row, ks * 2 + caf);
                ldm4(ah[mt], bufA_h + off);
                ldm4(al[mt], bufA_l + off);
            }

            int rb  = ((lane >> 4) & 1) * 8 + (lane & 7);
            int cbf = (lane >> 3) & 1;
#pragma unroll
            for (int p = 0; p < 2; ++p) {
                int row = wn + p * 16 + rb;
                uint32_t off = swz_off(row, ks * 2 + cbf);
                uint32_t t[4];
                ldm4(t, bufB_h + off);
                bh[p*2][0] = t[0]; bh[p*2][1] = t[1];
                bh[p*2+1][0] = t[2]; bh[p*2+1][1] = t[3];
                ldm4(t, bufB_l + off);
                bl[p*2][0] = t[0]; bl[p*2][1] = t[1];
                bl[p*2+1][0] = t[2]; bl[p*2+1][1] = t[3];
            }

#pragma unroll
            for (int mt = 0; mt < 4; ++mt)
#pragma unroll
                for (int nt = 0; nt < 4; ++nt) {
                    mma16816(acc[mt][nt], ah[mt], bh[nt]);
                    mma16816(acc[mt][nt], ah[mt], bl[nt]);
                    mma16816(acc[mt][nt], al[mt], bh[nt]);
                }
        }
        __syncthreads();
    }
}

// ============================================================
// Fused QKV GEMM: blockIdx.z selects Wq/Wk/Wv; fp32 outputs
// ============================================================
__global__ void __launch_bounds__(256) gemm_qkv(
    const __nv_bfloat16* __restrict__ xh, const __nv_bfloat16* __restrict__ xl,
    const __nv_bfloat16* __restrict__ wh, const __nv_bfloat16* __restrict__ wl,
    float* __restrict__ q, float* __restrict__ k, float* __restrict__ v)
{
    extern __shared__ char smem[];
    uint32_t sb = smem_u32(smem);
    int tid = threadIdx.x, lane = tid & 31, wid = tid >> 5;
    int m0 = blockIdx.y * 128, n0 = blockIdx.x * 128;
    int wm = (wid & 1) * 64, wn = (wid >> 1) * 32;
    int z = blockIdx.z;

    const __nv_bfloat16* Bh = wh + (size_t)z * DM * DM;
    const __nv_bfloat16* Bl = wl + (size_t)z * DM * DM;
    float* C = (z == 0) ? q : (z == 1) ? k : v;

    float acc[4][4][4];
#pragma unroll
    for (int a = 0; a < 4; a++)
#pragma unroll
        for (int b = 0; b < 4; b++)
#pragma unroll
            for (int c = 0; c < 4; c++) acc[a][b][c] = 0.0f;

    gemm_core(sb, xh, xl, Bh, Bl, m0, n0, DM, tid, lane, wm, wn, acc);

    int g = lane >> 2, c2 = (lane & 3) * 2;
#pragma unroll
    for (int mt = 0; mt < 4; ++mt)
#pragma unroll
        for (int nt = 0; nt < 4; ++nt) {
            int row = m0 + wm + mt * 16 + g;
            int col = n0 + wn + nt * 8 + c2;
            *reinterpret_cast<float2*>(C + (size_t)row * DM + col) =
                make_float2(acc[mt][nt][0], acc[mt][nt][1]);
            *reinterpret_cast<float2*>(C + (size_t)(row + 8) * DM + col) =
                make_float2(acc[mt][nt][2], acc[mt][nt][3]);
        }
}

// ============================================================
// Generic GEMM (fp32 out) — Wo projection
// ============================================================
__global__ void __launch_bounds__(256) gemm_mma(
    const __nv_bfloat16* __restrict__ Ah, const __nv_bfloat16* __restrict__ Al,
    const __nv_bfloat16* __restrict__ Bh, const __nv_bfloat16* __restrict__ Bl,
    float* __restrict__ C, int M, int N, int K)
{
    extern __shared__ char smem[];
    uint32_t sb = smem_u32(smem);
    int tid = threadIdx.x, lane = tid & 31, wid = tid >> 5;
    int m0 = blockIdx.y * 128, n0 = blockIdx.x * 128;
    int wm = (wid & 1) * 64, wn = (wid >> 1) * 32;

    float acc[4][4][4];
#pragma unroll
    for (int a = 0; a < 4; a++)
#pragma unroll
        for (int b = 0; b < 4; b++)
#pragma unroll
            for (int c = 0; c < 4; c++) acc[a][b][c] = 0.0f;

    gemm_core(sb, Ah, Al, Bh, Bl, m0, n0, K, tid, lane, wm, wn, acc);

    int g = lane >> 2, c2 = (lane & 3) * 2;
#pragma unroll
    for (int mt = 0; mt < 4; ++mt)
#pragma unroll
        for (int nt = 0; nt < 4; ++nt) {
            int row = m0 + wm + mt * 16 + g;
            int col = n0 + wn + nt * 8 + c2;
            *reinterpret_cast<float2*>(C + (size_t)row * N + col) =
                make_float2(acc[mt][nt][0], acc[mt][nt][1]);
            *reinterpret_cast<float2*>(C + (size_t)(row + 8) * N + col) =
                make_float2(acc[mt][nt][2], acc[mt][nt][3]);
        }
}

// ============================================================
// RoPE sin/cos table (fp64)
// ============================================================
__global__ void rope_table_kernel() {
    int i = blockIdx.x * blockDim.x + threadIdx.x;
    if (i >= TT * HALF_HD) return;
    int t = i / HALF_HD;
    int f = i % HALF_HD;
    double inv = exp(-((double)f / (double)HALF_HD) * log(10000.0));
    double ang = (double)t * inv;
    g_cos[i] = (float)cos(ang);
    g_sin[i] = (float)sin(ang);
}

// ============================================================
// RoPE + bf16 hi/lo split for Q,K (fused; fp32 in, bf16 out)
// ============================================================
__global__ void rope_split_kernel(const float* __restrict__ q, const float* __restrict__ k,
                                  __nv_bfloat16* __restrict__ qh, __nv_bfloat16* __restrict__ ql,
                                  __nv_bfloat16* __restrict__ kh, __nv_bfloat16* __restrict__ kl) {
    int i = blockIdx.x * blockDim.x + threadIdx.x;
    if (i >= BB * TT * NH * HALF_HD) return;
    int f    = i & (HALF_HD - 1);
    int rest = i >> 5;
    int h    = rest & (NH - 1);
    int bt   = rest >> 4;
    int t    = bt & (TT - 1);
    int off  = bt * DM + h * HD + f;
    float c = g_cos[t * HALF_HD + f];
    float s = g_sin[t * HALF_HD + f];

    float q1 = q[off], q2 = q[off + HALF_HD];
    float qa = q1 * c - q2 * s;
    float qb = q2 * c + q1 * s;
    __nv_bfloat16 ha = __float2bfloat16(qa);
    __nv_bfloat16 hb = __float2bfloat16(qb);
    qh[off] = ha;  qh[off + HALF_HD] = hb;
    ql[off] = __float2bfloat16(qa - __bfloat162float(ha));
    ql[off + HALF_HD] = __float2bfloat16(qb - __bfloat162float(hb));

    float k1 = k[off], k2 = k[off + HALF_HD];
    float ka = k1 * c - k2 * s;
    float kb = k2 * c + k1 * s;
    ha = __float2bfloat16(ka);
    hb = __float2bfloat16(kb);
    kh[off] = ha;  kh[off + HALF_HD] = hb;
    kl[off] = __float2bfloat16(ka - __bfloat162float(ha));
    kl[off + HALF_HD] = __float2bfloat16(kb - __bfloat162float(hb));
}

// ============================================================
// Tensor-core flash attention (causal, FA2-style, bf16x3)
// ============================================================
#define FA_SMEM 98304
#define FQH 0
#define FQL 16384
#define FKH 0
#define FKL 8192
#define FVH 16384
#define FVL 24576

__global__ void __launch_bounds__(256) flash_mma(
    const __nv_bfloat16* __restrict__ qh, const __nv_bfloat16* __restrict__ ql,
    const __nv_bfloat16* __restrict__ kh, const __nv_bfloat16* __restrict__ kl,
    const __nv_bfloat16* __restrict__ vh, const __nv_bfloat16* __restrict__ vl,
    float* __restrict__ O)
{
    extern __shared__ char smem[];
    uint32_t sb = smem_u32(smem);
    int tid = threadIdx.x, lane = tid & 31, w = tid >> 5;

    int qt = (int)gridDim.x - 1 - (int)blockIdx.x;
    int bh_ = blockIdx.y;
    int b = bh_ >> 4, h = bh_ & 15;
    size_t base = (size_t)b * TT * DM + h * HD;
    int q0 = qt * 128;

    const __nv_bfloat16* Qh = qh + base;
    const __nv_bfloat16* Ql = ql + base;
    const __nv_bfloat16* Kh = kh + base;
    const __nv_bfloat16* Kl = kl + base;
    const __nv_bfloat16* Vh = vh + base;
    const __nv_bfloat16* Vl = vl + base;

    for (int i = tid; i < 1024; i += 256) {
        int r = i >> 3, c = i & 7;
        size_t g = (size_t)(q0 + r) * DM + c * 8;
        cp16(sb + FQH + swz64(r, c), Qh + g);
        cp16(sb + FQL + swz64(r, c), Ql + g);
    }
    {
        uint32_t buf = sb + 32768;
        for (int i = tid; i < 512; i += 256) {
            int r = i >> 3, c = i & 7;
            size_t g = (size_t)r * DM + c * 8;
            uint32_t so = swz64(r, c);
            cp16(buf + FKH + so, Kh + g);
            cp16(buf + FKL + so, Kl + g);
            cp16(buf + FVH + so, Vh + g);
            cp16(buf + FVL + so, Vl + g);
        }
    }
    asm volatile("cp.async.commit_group;");

    const float NEG_INF = -__int_as_float(0x7f800000);
    float m0 = NEG_INF, m1 = NEG_INF, l0 = 0.0f, l1 = 0.0f;
    float o[8][4];
#pragma unroll
    for (int nt = 0; nt < 8; nt++)
#pragma unroll
        for (int c = 0; c < 4; c++) o[nt][c] = 0.0f;

    int nkt = 2 * qt + 2;
    int row0 = q0 + w * 16 + (lane >> 2);

    for (int kt = 0; kt < nkt; kt++) {
        uint32_t cur = sb + 32768u + (uint32_t)((kt & 1) * 32768);
        if (kt + 1 < nkt) {
            __syncthreads();
            uint32_t nb = sb + 32768u + (uint32_t)(((kt + 1) & 1) * 32768);
            int k0n = (kt + 1) * 64;
            for (int i = tid; i < 512; i += 256) {
                int r = i >> 3, c = i & 7;
                size_t g = (size_t)(k0n + r) * DM + c * 8;
                uint32_t so = swz64(r, c);
                cp16(nb + FKH + so, Kh + g);
                cp16(nb + FKL + so, Kl + g);
                cp16(nb + FVH + so, Vh + g);
                cp16(nb + FVL + so, Vl + g);
            }
            asm volatile("cp.async.commit_group;");
            asm volatile("cp.async.wait_group 1;");
        } else {
            asm volatile("cp.async.wait_group 0;");
        }
        __syncthreads();

        int k0 = kt * 64;

        float s[8][4];
#pragma unroll
        for (int nt = 0; nt < 8; nt++)
#pragma unroll
            for (int c = 0; c < 4; c++) s[nt][c] = 0.0f;

        int ra  = ((lane >> 3) & 1) * 8 + (lane & 7);
        int caf = (lane >> 4) & 1;
        int rb  = ((lane >> 4) & 1) * 8 + (lane & 7);
        int cbf = (lane >> 3) & 1;

#pragma unroll
        for (int ks = 0; ks < 4; ++ks) {
            uint32_t aH[4], aL[4];
            uint32_t qoff = swz64(w * 16 + ra, ks * 2 + caf);
            ldm4(aH, sb + FQH + qoff);
            ldm4(aL, sb + FQL + qoff);

            uint32_t bH[8][2], bL[8][2];
#pragma unroll
            for (int p = 0; p < 4; ++p) {
                uint32_t off = swz64(p * 16 + rb, ks * 2 + cbf);
                uint32_t t[4];
                ldm4(t, cur + FKH + off);
                bH[p*2][0] = t[0]; bH[p*2][1] = t[1];
                bH[p*2+1][0] = t[2]; bH[p*2+1][1] = t[3];
                ldm4(t, cur + FKL + off);
                bL[p*2][0] = t[0]; bL[p*2][1] = t[1];
                bL[p*2+1][0] = t[2]; bL[p*2+1][1] = t[3];
            }
#pragma unroll
            for (int nt = 0; nt < 8; ++nt) {
                mma16816(s[nt], aH, bH[nt]);
                mma16816(s[nt], aH, bL[nt]);
                mma16816(s[nt], aL, bH[nt]);
            }
        }

        bool needmask = (k0 + 63 > q0);
#pragma unroll
        for (int nt = 0; nt < 8; ++nt) {
#pragma unroll
            for (int c = 0; c < 4; ++c) {
                float v = s[nt][c] * 0.125f;
                if (needmask) {
                    int col = k0 + nt * 8 + (lane & 3) * 2 + (c & 1);
                    int rowg = row0 + ((c >> 1) << 3);
                    if (col > rowg) v = NEG_INF;
                }
                s[nt][c] = v;
            }
        }

        float mx0 = NEG_INF, mx1 = NEG_INF;
#pragma unroll
        for (int nt = 0; nt < 8; ++nt) {
            mx0 = fmaxf(mx0, fmaxf(s[nt][0], s[nt][1]));
            mx1 = fmaxf(mx1, fmaxf(s[nt][2], s[nt][3]));
        }
        mx0 = fmaxf(mx0, __shfl_xor_sync(0xffffffffu, mx0, 1));
        mx0 = fmaxf(mx0, __shfl_xor_sync(0xffffffffu, mx0, 2));
        mx1 = fmaxf(mx1, __shfl_xor_sync(0xffffffffu, mx1, 1));
        mx1 = fmaxf(mx1, __shfl_xor_sync(0xffffffffu, mx1, 2));

        float mn0 = fmaxf(m0, mx0), mn1 = fmaxf(m1, mx1);
        float al0 = __expf(m0 - mn0), al1 = __expf(m1 - mn1);
        if (m0 == NEG_INF && mn0 == NEG_INF) al0 = 1.0f;
        if (m1 == NEG_INF && mn1 == NEG_INF) al1 = 1.0f;
        m0 = mn0; m1 = mn1;

        float ls0 = 0.0f, ls1 = 0.0f;
#pragma unroll
        for (int nt = 0; nt < 8; ++nt) {
            float p0 = (s[nt][0] == NEG_INF) ? 0.0f : __expf(s[nt][0] - mn0);
            float p1 = (s[nt][1] == NEG_INF) ? 0.0f : __expf(s[nt][1] - mn0);
            float p2 = (s[nt][2] == NEG_INF) ? 0.0f : __expf(s[nt][2] - mn1);
            float p3 = (s[nt][3] == NEG_INF) ? 0.0f : __expf(s[nt][3] - mn1);
            s[nt][0] = p0; s[nt][1] = p1; s[nt][2] = p2; s[nt][3] = p3;
            ls0 += p0 + p1; ls1 += p2 + p3;
        }
        ls0 += __shfl_xor_sync(0xffffffffu, ls0, 1);
        ls0 += __shfl_xor_sync(0xffffffffu, ls0, 2);
        ls1 += __shfl_xor_sync(0xffffffffu, ls1, 1);
        ls1 += __shfl_xor_sync(0xffffffffu, ls1, 2);
        l0 = l0 * al0 + ls0;
        l1 = l1 * al1 + ls1;

#pragma unroll
        for (int nt = 0; nt < 8; ++nt) {
            o[nt][0] *= al0; o[nt][1] *= al0;
            o[nt][2] *= al1; o[nt][3] *= al1;
        }

#pragma unroll
        for (int ks = 0; ks < 4; ++ks) {
            uint32_t pH[4], pL[4];
            splitpack(s[2*ks][0],   s[2*ks][1],   pH[0], pL[0]);
            splitpack(s[2*ks][2],   s[2*ks][3],   pH[1], pL[1]);
            splitpack(s[2*ks+1][0], s[2*ks+1][1], pH[2], pL[2]);
            splitpack(s[2*ks+1][2], s[2*ks+1][3], pH[3], pL[3]);

            int mm = lane >> 3, la = lane & 7;
            int vrow = ks * 16 + (mm & 1) * 8 + la;
#pragma unroll
            for (int ntp = 0; ntp < 4; ++ntp) {
                int vchunk = ntp * 2 + (mm >> 1);
                uint32_t off = swz64(vrow, vchunk);
                uint32_t tH[4], tL[4];
                ldm4t(tH, cur + FVH + off);
                ldm4t(tL, cur + FVL + off);
                uint32_t b0H[2] = {tH[0], tH[1]}, b1H[2] = {tH[2], tH[3]};
                uint32_t b0L[2] = {tL[0], tL[1]}, b1L[2] = {tL[2], tL[3]};
                mma16816(o[2*ntp],   pH, b0H);
                mma16816(o[2*ntp],   pH, b0L);
                mma16816(o[2*ntp],   pL, b0H);
                mma16816(o[2*ntp+1], pH, b1H);
                mma16816(o[2*ntp+1], pH, b1L);
                mma16816(o[2*ntp+1], pL, b1H);
            }
        }
    }

    float inv0 = 1.0f / l0, inv1 = 1.0f / l1;
    float* Op = O + base;
    int c2 = (lane & 3) * 2;
#pragma unroll
    for (int nt = 0; nt < 8; ++nt) {
        *reinterpret_cast<float2*>(Op + (size_t)row0 * DM + nt * 8 + c2) =
            make_float2(o[nt][0] * inv0, o[nt][1] * inv0);
        *reinterpret_cast<float2*>(Op + (size_t)(row0 + 8) * DM + nt * 8 + c2) =
            make_float2(o[nt][2] * inv1, o[nt][3] * inv1);
    }
}

// ============================================================
// launch
// ============================================================
extern "C" void kernel_launch(void* const* d_in, const int* in_sizes, int n_in,
                              void* d_out, int out_size) {
    const float* x  = (const float*)d_in[0];
    const float* Wq = (const float*)d_in[1];
    const float* Wk = (const float*)d_in[2];
    const float* Wv = (const float*)d_in[3];
    const float* Wo = (const float*)d_in[4];
    float* out = (float*)d_out;

    float *q, *k, *v;
    cudaGetSymbolAddress((void**)&q,  g_q);
    cudaGetSymbolAddress((void**)&k,  g_k);
    cudaGetSymbolAddress((void**)&v,  g_v);

    __nv_bfloat16 *xh, *xl, *aoh, *aol, *wh, *wl;
    __nv_bfloat16 *qh, *ql, *kh, *kl, *vh, *vl;
    cudaGetSymbolAddress((void**)&xh,  g_xh);
    cudaGetSymbolAddress((void**)&xl,  g_xl);
    cudaGetSymbolAddress((void**)&aoh, g_aoh);
    cudaGetSymbolAddress((void**)&aol, g_aol);
    cudaGetSymbolAddress((void**)&wh,  g_wh);
    cudaGetSymbolAddress((void**)&wl,  g_wl);
    cudaGetSymbolAddress((void**)&qh,  g_qh);
    cudaGetSymbolAddress((void**)&ql,  g_ql);
    cudaGetSymbolAddress((void**)&kh,  g_kh);
    cudaGetSymbolAddress((void**)&kl,  g_kl);
    cudaGetSymbolAddress((void**)&vh,  g_vh);
    cudaGetSymbolAddress((void**)&vl,  g_vl);

    cudaFuncSetAttribute(gemm_qkv,  cudaFuncAttributeMaxDynamicSharedMemorySize, GM_SMEM);
    cudaFuncSetAttribute(gemm_mma,  cudaFuncAttributeMaxDynamicSharedMemorySize, GM_SMEM);
    cudaFuncSetAttribute(flash_mma, cudaFuncAttributeMaxDynamicSharedMemorySize, FA_SMEM);

    rope_table_kernel<<<(TT * HALF_HD + 255) / 256, 256>>>();

    int nx4 = MROWS * DM / 4;
    int nw4 = DM * DM / 4;
    split_kernel<<<(nx4 + 255) / 256, 256>>>(x, xh, xl, nx4);
    split_kernel<<<(nw4 + 255) / 256, 256>>>(Wq, wh + 0 * (size_t)DM * DM, wl + 0 * (size_t)DM * DM, nw4);
    split_kernel<<<(nw4 + 255) / 256, 256>>>(Wk, wh + 1 * (size_t)DM * DM, wl + 1 * (size_t)DM * DM, nw4);
    split_kernel<<<(nw4 + 255) / 256, 256>>>(Wv, wh + 2 * (size_t)DM * DM, wl + 2 * (size_t)DM * DM, nw4);
    split_kernel<<<(nw4 + 255) / 256, 256>>>(Wo, wh + 3 * (size_t)DM * DM, wl + 3 * (size_t)DM * DM, nw4);

    // fused QKV projections — ONE launch, fp32 outputs
    gemm_qkv<<<dim3(DM / 128, MROWS / 128, 3), 256, GM_SMEM>>>(
        xh, xl, wh, wl, q, k, v);

    rope_split_kernel<<<(BB * TT * NH * HALF_HD + 255) / 256, 256>>>(q, k, qh, ql, kh, kl);
    split_kernel<<<(nx4 + 255) / 256, 256>>>(v, vh, vl, nx4);

    // flash output -> device scratch q (proper device pointer!), then split
    flash_mma<<<dim3(TT / 128, BB * NH), 256, FA_SMEM>>>(qh, ql, kh, kl, vh, vl, q);

    split_kernel<<<(nx4 + 255) / 256, 256>>>(q, aoh, aol, nx4);
    gemm_mma<<<dim3(DM / 128, MROWS / 128), 256, GM_SMEM>>>(
        aoh, aol, wh + 3 * (size_t)DM * DM, wl + 3 * (size_t)DM * DM, out, MROWS, DM, DM);
}

// round 13
// speedup vs baseline: 1.4968x; 1.0010x over previous
#include <cuda_runtime.h>
#include <cuda_bf16.h>
#include <stdint.h>
#include <math.h>

#define BB 4
#define TT 2048
#define DM 1024
#define NH 16
#define HD 64
#define MROWS (BB*TT)          // 8192
#define HALF_HD (HD/2)         // 32

// -------- scratch (no cudaMalloc allowed) --------
__device__ float g_q[MROWS*DM];
__device__ float g_k[MROWS*DM];
__device__ float g_v[MROWS*DM];
__device__ float g_cos[TT*HALF_HD];
__device__ float g_sin[TT*HALF_HD];

// bf16 split operands
__device__ __nv_bfloat16 g_xh[MROWS*DM];
__device__ __nv_bfloat16 g_xl[MROWS*DM];
__device__ __nv_bfloat16 g_aoh[MROWS*DM];
__device__ __nv_bfloat16 g_aol[MROWS*DM];
__device__ __nv_bfloat16 g_wh[4][DM*DM];
__device__ __nv_bfloat16 g_wl[4][DM*DM];
// attention operands (post-rope)
__device__ __nv_bfloat16 g_qh[MROWS*DM];
__device__ __nv_bfloat16 g_ql[MROWS*DM];
__device__ __nv_bfloat16 g_kh[MROWS*DM];
__device__ __nv_bfloat16 g_kl[MROWS*DM];
__device__ __nv_bfloat16 g_vh[MROWS*DM];
__device__ __nv_bfloat16 g_vl[MROWS*DM];

// ============================================================
// helpers
// ============================================================
__device__ __forceinline__ uint32_t smem_u32(const void* p) {
    uint32_t a;
    asm("{ .reg .u64 t; cvta.to.shared.u64 t, %1; cvt.u32.u64 %0, t; }"
        : "=r"(a) : "l"(p));
    return a;
}

__device__ __forceinline__ void ldm4(uint32_t r[4], uint32_t addr) {
    asm volatile("ldmatrix.sync.aligned.m8n8.x4.shared.b16 {%0,%1,%2,%3}, [%4];"
                 : "=r"(r[0]), "=r"(r[1]), "=r"(r[2]), "=r"(r[3]) : "r"(addr));
}
__device__ __forceinline__ void ldm4t(uint32_t r[4], uint32_t addr) {
    asm volatile("ldmatrix.sync.aligned.m8n8.x4.trans.shared.b16 {%0,%1,%2,%3}, [%4];"
                 : "=r"(r[0]), "=r"(r[1]), "=r"(r[2]), "=r"(r[3]) : "r"(addr));
}

__device__ __forceinline__ void mma16816(float c[4], const uint32_t a[4], const uint32_t b[2]) {
    asm volatile("mma.sync.aligned.m16n8k16.row.col.f32.bf16.bf16.f32 "
                 "{%0,%1,%2,%3}, {%4,%5,%6,%7}, {%8,%9}, {%0,%1,%2,%3};"
                 : "+f"(c[0]), "+f"(c[1]), "+f"(c[2]), "+f"(c[3])
                 : "r"(a[0]), "r"(a[1]), "r"(a[2]), "r"(a[3]), "r"(b[0]), "r"(b[1]));
}

__device__ __forceinline__ void cp16(uint32_t s, const void* g) {
    asm volatile("cp.async.cg.shared.global [%0], [%1], 16;" :: "r"(s), "l"(g));
}

// 32-col (64B row) tile swizzle — gemm tiles (proven)
__device__ __forceinline__ uint32_t swz_off(int row, int chunk) {
    return (uint32_t)(row * 64 + ((chunk ^ (row & 3) ^ ((row >> 2) & 3)) << 4));
}
// 64-col (128B row) tile swizzle — attention tiles (proven)
__device__ __forceinline__ uint32_t swz64(int row, int chunk) {
    return (uint32_t)(row * 128 + (((chunk ^ (row & 7)) & 7) << 4));
}

__device__ __forceinline__ void tile_cp(uint32_t sbase, const __nv_bfloat16* __restrict__ src,
                                        int row0, int K, int kc, int tid) {
#pragma unroll
    for (int it = 0; it < 2; ++it) {
        int idx = tid + it * 256;
        int r = idx >> 2, c = idx & 3;
        uint32_t soff = sbase + swz_off(r, c);
        const void* g = src + (size_t)(row0 + r) * K + kc + c * 8;
        cp16(soff, g);
    }
}

// pack two fp32 -> bf16x2 hi and residual-lo regs
__device__ __forceinline__ void splitpack(float p0, float p1, uint32_t& h, uint32_t& l) {
    __nv_bfloat16 h0 = __float2bfloat16(p0);
    __nv_bfloat16 h1 = __float2bfloat16(p1);
    __nv_bfloat16 l0 = __float2bfloat16(p0 - __bfloat162float(h0));
    __nv_bfloat16 l1 = __float2bfloat16(p1 - __bfloat162float(h1));
    __nv_bfloat162 hh(h0, h1), ll(l0, l1);
    h = *reinterpret_cast<uint32_t*>(&hh);
    l = *reinterpret_cast<uint32_t*>(&ll);
}

// ============================================================
// fp32 -> bf16 hi/lo split
// ============================================================
__global__ void split_kernel(const float* __restrict__ src,
                             __nv_bfloat16* __restrict__ hi,
                             __nv_bfloat16* __restrict__ lo, int n4) {
    int i = blockIdx.x * blockDim.x + threadIdx.x;
    if (i >= n4) return;
    float4 x = reinterpret_cast<const float4*>(src)[i];
    __nv_bfloat16 h0 = __float2bfloat16(x.x);
    __nv_bfloat16 h1 = __float2bfloat16(x.y);
    __nv_bfloat16 h2 = __float2bfloat16(x.z);
    __nv_bfloat16 h3 = __float2bfloat16(x.w);
    __nv_bfloat16 l0 = __float2bfloat16(x.x - __bfloat162float(h0));
    __nv_bfloat16 l1 = __float2bfloat16(x.y - __bfloat162float(h1));
    __nv_bfloat16 l2 = __float2bfloat16(x.z - __bfloat162float(h2));
    __nv_bfloat16 l3 = __float2bfloat16(x.w - __bfloat162float(h3));
    __nv_bfloat162* hp = reinterpret_cast<__nv_bfloat162*>(hi);
    __nv_bfloat162* lp = reinterpret_cast<__nv_bfloat162*>(lo);
    hp[2*i]   = __nv_bfloat162(h0, h1);
    hp[2*i+1] = __nv_bfloat162(h2, h3);
    lp[2*i]   = __nv_bfloat162(l0, l1);
    lp[2*i+1] = __nv_bfloat162(l2, l3);
}

// ============================================================
// GEMM mainloop core — 3-stage cp.async pipeline, ONE barrier
// per K-chunk. Buffers: stage = ch % 3, 32KB apart.
// Safety: load for chunk ch+2 is issued AFTER the iter-ch
// barrier; all warps passed that barrier only after finishing
// compute of iter ch-1, which is the last reader of that buffer.
// ============================================================
#define GM_SMEM (3*32768)

__device__ __forceinline__ void load_chunk(
    uint32_t buf, const __nv_bfloat16* Ah, const __nv_bfloat16* Al,
    const __nv_bfloat16* Bh, const __nv_bfloat16* Bl,
    int m0, int n0, int K, int kc, int tid)
{
    tile_cp(buf +     0, Ah, m0, K, kc, tid);
    tile_cp(buf +  8192, Al, m0, K, kc, tid);
    tile_cp(buf + 16384, Bh, n0, K, kc, tid);
    tile_cp(buf + 24576, Bl, n0, K, kc, tid);
    asm volatile("cp.async.commit_group;");
}

__device__ __forceinline__ void gemm_core(
    uint32_t sb, const __nv_bfloat16* Ah, const __nv_bfloat16* Al,
    const __nv_bfloat16* Bh, const __nv_bfloat16* Bl,
    int m0, int n0, int K, int tid, int lane,
    int wm, int wn, float acc[4][4][4])
{
    const int nch = K / 32;   // >= 2 for all our shapes

    load_chunk(sb,          Ah, Al, Bh, Bl, m0, n0, K,  0, tid);
    load_chunk(sb + 32768,  Ah, Al, Bh, Bl, m0, n0, K, 32, tid);

    for (int ch = 0; ch < nch; ++ch) {
        if (ch + 1 < nch) {
            asm volatile("cp.async.wait_group 1;");
        } else {
            asm volatile("cp.async.wait_group 0;");
        }
        __syncthreads();

        if (ch + 2 < nch) {
            uint32_t nb = sb + (uint32_t)(((ch + 2) % 3) * 32768);
            load_chunk(nb, Ah, Al, Bh, Bl, m0, n0, K, (ch + 2) * 32, tid);
        }

        uint32_t bufA_h = sb + (uint32_t)((ch % 3) * 32768);
        uint32_t bufA_l = bufA_h + 8192;
        uint32_t bufB_h = bufA_h + 16384;
        uint32_t bufB_l = bufA_h + 24576;

#pragma unroll
        for (int ks = 0; ks < 2; ++ks) {
            uint32_t ah[4][4], al[4][4], bh[4][2], bl[4][2];

            int ra  = ((lane >> 3) & 1) * 8 + (lane & 7);
            int caf = (lane >> 4) & 1;
#pragma unroll
            for (int mt = 0; mt < 4; ++mt) {
                int row = wm + mt * 16 + ra;
                uint32_t off = swz_off(row, ks * 2 + caf);
                ldm4(ah[mt], bufA_h + off);
                ldm4(al[mt], bufA_l + off);
            }

            int rb  = ((lane >> 4) & 1) * 8 + (lane & 7);
            int cbf = (lane >> 3) & 1;
#pragma unroll
            for (int p = 0; p < 2; ++p) {
                int row = wn + p * 16 + rb;
                uint32_t off = swz_off(row, ks * 2 + cbf);
                uint32_t t[4];
                ldm4(t, bufB_h + off);
                bh[p*2][0] = t[0]; bh[p*2][1] = t[1];
                bh[p*2+1][0] = t[2]; bh[p*2+1][1] = t[3];
                ldm4(t, bufB_l + off);
                bl[p*2][0] = t[0]; bl[p*2][1] = t[1];
                bl[p*2+1][0] = t[2]; bl[p*2+1][1] = t[3];
            }

#pragma unroll
            for (int mt = 0; mt < 4; ++mt)
#pragma unroll
                for (int nt = 0; nt < 4; ++nt) {
                    mma16816(acc[mt][nt], ah[mt], bh[nt]);
                    mma16816(acc[mt][nt], ah[mt], bl[nt]);
                    mma16816(acc[mt][nt], al[mt], bh[nt]);
                }
        }
        // no trailing barrier — next iteration's top barrier protects
    }
    __syncthreads();   // protect smem reuse after return (epilogue-free here)
}

// ============================================================
// Fused QKV GEMM: blockIdx.z selects Wq/Wk/Wv; fp32 outputs
// ============================================================
__global__ void __launch_bounds__(256) gemm_qkv(
    const __nv_bfloat16* __restrict__ xh, const __nv_bfloat16* __restrict__ xl,
    const __nv_bfloat16* __restrict__ wh, const __nv_bfloat16* __restrict__ wl,
    float* __restrict__ q, float* __restrict__ k, float* __restrict__ v)
{
    extern __shared__ char smem[];
    uint32_t sb = smem_u32(smem);
    int tid = threadIdx.x, lane = tid & 31, wid = tid >> 5;
    int m0 = blockIdx.y * 128, n0 = blockIdx.x * 128;
    int wm = (wid & 1) * 64, wn = (wid >> 1) * 32;
    int z = blockIdx.z;

    const __nv_bfloat16* Bh = wh + (size_t)z * DM * DM;
    const __nv_bfloat16* Bl = wl + (size_t)z * DM * DM;
    float* C = (z == 0) ? q : (z == 1) ? k : v;

    float acc[4][4][4];
#pragma unroll
    for (int a = 0; a < 4; a++)
#pragma unroll
        for (int b = 0; b < 4; b++)
#pragma unroll
            for (int c = 0; c < 4; c++) acc[a][b][c] = 0.0f;

    gemm_core(sb, xh, xl, Bh, Bl, m0, n0, DM, tid, lane, wm, wn, acc);

    int g = lane >> 2, c2 = (lane & 3) * 2;
#pragma unroll
    for (int mt = 0; mt < 4; ++mt)
#pragma unroll
        for (int nt = 0; nt < 4; ++nt) {
            int row = m0 + wm + mt * 16 + g;
            int col = n0 + wn + nt * 8 + c2;
            *reinterpret_cast<float2*>(C + (size_t)row * DM + col) =
                make_float2(acc[mt][nt][0], acc[mt][nt][1]);
            *reinterpret_cast<float2*>(C + (size_t)(row + 8) * DM + col) =
                make_float2(acc[mt][nt][2], acc[mt][nt][3]);
        }
}

// ============================================================
// Generic GEMM (fp32 out) — Wo projection
// ============================================================
__global__ void __launch_bounds__(256) gemm_mma(
    const __nv_bfloat16* __restrict__ Ah, const __nv_bfloat16* __restrict__ Al,
    const __nv_bfloat16* __restrict__ Bh, const __nv_bfloat16* __restrict__ Bl,
    float* __restrict__ C, int M, int N, int K)
{
    extern __shared__ char smem[];
    uint32_t sb = smem_u32(smem);
    int tid = threadIdx.x, lane = tid & 31, wid = tid >> 5;
    int m0 = blockIdx.y * 128, n0 = blockIdx.x * 128;
    int wm = (wid & 1) * 64, wn = (wid >> 1) * 32;

    float acc[4][4][4];
#pragma unroll
    for (int a = 0; a < 4; a++)
#pragma unroll
        for (int b = 0; b < 4; b++)
#pragma unroll
            for (int c = 0; c < 4; c++) acc[a][b][c] = 0.0f;

    gemm_core(sb, Ah, Al, Bh, Bl, m0, n0, K, tid, lane, wm, wn, acc);

    int g = lane >> 2, c2 = (lane & 3) * 2;
#pragma unroll
    for (int mt = 0; mt < 4; ++mt)
#pragma unroll
        for (int nt = 0; nt < 4; ++nt) {
            int row = m0 + wm + mt * 16 + g;
            int col = n0 + wn + nt * 8 + c2;
            *reinterpret_cast<float2*>(C + (size_t)row * N + col) =
                make_float2(acc[mt][nt][0], acc[mt][nt][1]);
            *reinterpret_cast<float2*>(C + (size_t)(row + 8) * N + col) =
                make_float2(acc[mt][nt][2], acc[mt][nt][3]);
        }
}

// ============================================================
// RoPE sin/cos table (fp64)
// ============================================================
__global__ void rope_table_kernel() {
    int i = blockIdx.x * blockDim.x + threadIdx.x;
    if (i >= TT * HALF_HD) return;
    int t = i / HALF_HD;
    int f = i % HALF_HD;
    double inv = exp(-((double)f / (double)HALF_HD) * log(10000.0));
    double ang = (double)t * inv;
    g_cos[i] = (float)cos(ang);
    g_sin[i] = (float)sin(ang);
}

// ============================================================
// RoPE + bf16 hi/lo split for Q,K (fused; fp32 in, bf16 out)
// ============================================================
__global__ void rope_split_kernel(const float* __restrict__ q, const float* __restrict__ k,
                                  __nv_bfloat16* __restrict__ qh, __nv_bfloat16* __restrict__ ql,
                                  __nv_bfloat16* __restrict__ kh, __nv_bfloat16* __restrict__ kl) {
    int i = blockIdx.x * blockDim.x + threadIdx.x;
    if (i >= BB * TT * NH * HALF_HD) return;
    int f    = i & (HALF_HD - 1);
    int rest = i >> 5;
    int h    = rest & (NH - 1);
    int bt   = rest >> 4;
    int t    = bt & (TT - 1);
    int off  = bt * DM + h * HD + f;
    float c = g_cos[t * HALF_HD + f];
    float s = g_sin[t * HALF_HD + f];

    float q1 = q[off], q2 = q[off + HALF_HD];
    float qa = q1 * c - q2 * s;
    float qb = q2 * c + q1 * s;
    __nv_bfloat16 ha = __float2bfloat16(qa);
    __nv_bfloat16 hb = __float2bfloat16(qb);
    qh[off] = ha;  qh[off + HALF_HD] = hb;
    ql[off] = __float2bfloat16(qa - __bfloat162float(ha));
    ql[off + HALF_HD] = __float2bfloat16(qb - __bfloat162float(hb));

    float k1 = k[off], k2 = k[off + HALF_HD];
    float ka = k1 * c - k2 * s;
    float kb = k2 * c + k1 * s;
    ha = __float2bfloat16(ka);
    hb = __float2bfloat16(kb);
    kh[off] = ha;  kh[off + HALF_HD] = hb;
    kl[off] = __float2bfloat16(ka - __bfloat162float(ha));
    kl[off + HALF_HD] = __float2bfloat16(kb - __bfloat162float(hb));
}

// ============================================================
// Tensor-core flash attention (causal, FA2-style, bf16x3)
// ============================================================
#define FA_SMEM 98304
#define FQH 0
#define FQL 16384
#define FKH 0
#define FKL 8192
#define FVH 16384
#define FVL 24576

__global__ void __launch_bounds__(256) flash_mma(
    const __nv_bfloat16* __restrict__ qh, const __nv_bfloat16* __restrict__ ql,
    const __nv_bfloat16* __restrict__ kh, const __nv_bfloat16* __restrict__ kl,
    const __nv_bfloat16* __restrict__ vh, const __nv_bfloat16* __restrict__ vl,
    float* __restrict__ O)
{
    extern __shared__ char smem[];
    uint32_t sb = smem_u32(smem);
    int tid = threadIdx.x, lane = tid & 31, w = tid >> 5;

    int qt = (int)gridDim.x - 1 - (int)blockIdx.x;
    int bh_ = blockIdx.y;
    int b = bh_ >> 4, h = bh_ & 15;
    size_t base = (size_t)b * TT * DM + h * HD;
    int q0 = qt * 128;

    const __nv_bfloat16* Qh = qh + base;
    const __nv_bfloat16* Ql = ql + base;
    const __nv_bfloat16* Kh = kh + base;
    const __nv_bfloat16* Kl = kl + base;
    const __nv_bfloat16* Vh = vh + base;
    const __nv_bfloat16* Vl = vl + base;

    for (int i = tid; i < 1024; i += 256) {
        int r = i >> 3, c = i & 7;
        size_t g = (size_t)(q0 + r) * DM + c * 8;
        cp16(sb + FQH + swz64(r, c), Qh + g);
        cp16(sb + FQL + swz64(r, c), Ql + g);
    }
    {
        uint32_t buf = sb + 32768;
        for (int i = tid; i < 512; i += 256) {
            int r = i >> 3, c = i & 7;
            size_t g = (size_t)r * DM + c * 8;
            uint32_t so = swz64(r, c);
            cp16(buf + FKH + so, Kh + g);
            cp16(buf + FKL + so, Kl + g);
            cp16(buf + FVH + so, Vh + g);
            cp16(buf + FVL + so, Vl + g);
        }
    }
    asm volatile("cp.async.commit_group;");

    const float NEG_INF = -__int_as_float(0x7f800000);
    float m0 = NEG_INF, m1 = NEG_INF, l0 = 0.0f, l1 = 0.0f;
    float o[8][4];
#pragma unroll
    for (int nt = 0; nt < 8; nt++)
#pragma unroll
        for (int c = 0; c < 4; c++) o[nt][c] = 0.0f;

    int nkt = 2 * qt + 2;
    int row0 = q0 + w * 16 + (lane >> 2);

    for (int kt = 0; kt < nkt; kt++) {
        uint32_t cur = sb + 32768u + (uint32_t)((kt & 1) * 32768);
        if (kt + 1 < nkt) {
            __syncthreads();
            uint32_t nb = sb + 32768u + (uint32_t)(((kt + 1) & 1) * 32768);
            int k0n = (kt + 1) * 64;
            for (int i = tid; i < 512; i += 256) {
                int r = i >> 3, c = i & 7;
                size_t g = (size_t)(k0n + r) * DM + c * 8;
                uint32_t so = swz64(r, c);
                cp16(nb + FKH + so, Kh + g);
                cp16(nb + FKL + so, Kl + g);
                cp16(nb + FVH + so, Vh + g);
                cp16(nb + FVL + so, Vl + g);
            }
            asm volatile("cp.async.commit_group;");
            asm volatile("cp.async.wait_group 1;");
        } else {
            asm volatile("cp.async.wait_group 0;");
        }
        __syncthreads();

        int k0 = kt * 64;

        float s[8][4];
#pragma unroll
        for (int nt = 0; nt < 8; nt++)
#pragma unroll
            for (int c = 0; c < 4; c++) s[nt][c] = 0.0f;

        int ra  = ((lane >> 3) & 1) * 8 + (lane & 7);
        int caf = (lane >> 4) & 1;
        int rb  = ((lane >> 4) & 1) * 8 + (lane & 7);
        int cbf = (lane >> 3) & 1;

#pragma unroll
        for (int ks = 0; ks < 4; ++ks) {
            uint32_t aH[4], aL[4];
            uint32_t qoff = swz64(w * 16 + ra, ks * 2 + caf);
            ldm4(aH, sb + FQH + qoff);
            ldm4(aL, sb + FQL + qoff);

            uint32_t bH[8][2], bL[8][2];
#pragma unroll
            for (int p = 0; p < 4; ++p) {
                uint32_t off = swz64(p * 16 + rb, ks * 2 + cbf);
                uint32_t t[4];
                ldm4(t, cur + FKH + off);
                bH[p*2][0] = t[0]; bH[p*2][1] = t[1];
                bH[p*2+1][0] = t[2]; bH[p*2+1][1] = t[3];
                ldm4(t, cur + FKL + off);
                bL[p*2][0] = t[0]; bL[p*2][1] = t[1];
                bL[p*2+1][0] = t[2]; bL[p*2+1][1] = t[3];
            }
#pragma unroll
            for (int nt = 0; nt < 8; ++nt) {
                mma16816(s[nt], aH, bH[nt]);
                mma16816(s[nt], aH, bL[nt]);
                mma16816(s[nt], aL, bH[nt]);
            }
        }

        bool needmask = (k0 + 63 > q0);
#pragma unroll
        for (int nt = 0; nt < 8; ++nt) {
#pragma unroll
            for (int c = 0; c < 4; ++c) {
                float v = s[nt][c] * 0.125f;
                if (needmask) {
                    int col = k0 + nt * 8 + (lane & 3) * 2 + (c & 1);
                    int rowg = row0 + ((c >> 1) << 3);
                    if (col > rowg) v = NEG_INF;
                }
                s[nt][c] = v;
            }
        }

        float mx0 = NEG_INF, mx1 = NEG_INF;
#pragma unroll
        for (int nt = 0; nt < 8; ++nt) {
            mx0 = fmaxf(mx0, fmaxf(s[nt][0], s[nt][1]));
            mx1 = fmaxf(mx1, fmaxf(s[nt][2], s[nt][3]));
        }
        mx0 = fmaxf(mx0, __shfl_xor_sync(0xffffffffu, mx0, 1));
        mx0 = fmaxf(mx0, __shfl_xor_sync(0xffffffffu, mx0, 2));
        mx1 = fmaxf(mx1, __shfl_xor_sync(0xffffffffu, mx1, 1));
        mx1 = fmaxf(mx1, __shfl_xor_sync(0xffffffffu, mx1, 2));

        float mn0 = fmaxf(m0, mx0), mn1 = fmaxf(m1, mx1);
        float al0 = __expf(m0 - mn0), al1 = __expf(m1 - mn1);
        if (m0 == NEG_INF && mn0 == NEG_INF) al0 = 1.0f;
        if (m1 == NEG_INF && mn1 == NEG_INF) al1 = 1.0f;
        m0 = mn0; m1 = mn1;

        float ls0 = 0.0f, ls1 = 0.0f;
#pragma unroll
        for (int nt = 0; nt < 8; ++nt) {
            float p0 = (s[nt][0] == NEG_INF) ? 0.0f : __expf(s[nt][0] - mn0);
            float p1 = (s[nt][1] == NEG_INF) ? 0.0f : __expf(s[nt][1] - mn0);
            float p2 = (s[nt][2] == NEG_INF) ? 0.0f : __expf(s[nt][2] - mn1);
            float p3 = (s[nt][3] == NEG_INF) ? 0.0f : __expf(s[nt][3] - mn1);
            s[nt][0] = p0; s[nt][1] = p1; s[nt][2] = p2; s[nt][3] = p3;
            ls0 += p0 + p1; ls1 += p2 + p3;
        }
        ls0 += __shfl_xor_sync(0xffffffffu, ls0, 1);
        ls0 += __shfl_xor_sync(0xffffffffu, ls0, 2);
        ls1 += __shfl_xor_sync(0xffffffffu, ls1, 1);
        ls1 += __shfl_xor_sync(0xffffffffu, ls1, 2);
        l0 = l0 * al0 + ls0;
        l1 = l1 * al1 + ls1;

#pragma unroll
        for (int nt = 0; nt < 8; ++nt) {
            o[nt][0] *= al0; o[nt][1] *= al0;
            o[nt][2] *= al1; o[nt][3] *= al1;
        }

#pragma unroll
        for (int ks = 0; ks < 4; ++ks) {
            uint32_t pH[4], pL[4];
            splitpack(s[2*ks][0],   s[2*ks][1],   pH[0], pL[0]);
            splitpack(s[2*ks][2],   s[2*ks][3],   pH[1], pL[1]);
            splitpack(s[2*ks+1][0], s[2*ks+1][1], pH[2], pL[2]);
            splitpack(s[2*ks+1][2], s[2*ks+1][3], pH[3], pL[3]);

            int mm = lane >> 3, la = lane & 7;
            int vrow = ks * 16 + (mm & 1) * 8 + la;
#pragma unroll
            for (int ntp = 0; ntp < 4; ++ntp) {
                int vchunk = ntp * 2 + (mm >> 1);
                uint32_t off = swz64(vrow, vchunk);
                uint32_t tH[4], tL[4];
                ldm4t(tH, cur + FVH + off);
                ldm4t(tL, cur + FVL + off);
                uint32_t b0H[2] = {tH[0], tH[1]}, b1H[2] = {tH[2], tH[3]};
                uint32_t b0L[2] = {tL[0], tL[1]}, b1L[2] = {tL[2], tL[3]};
                mma16816(o[2*ntp],   pH, b0H);
                mma16816(o[2*ntp],   pH, b0L);
                mma16816(o[2*ntp],   pL, b0H);
                mma16816(o[2*ntp+1], pH, b1H);
                mma16816(o[2*ntp+1], pH, b1L);
                mma16816(o[2*ntp+1], pL, b1H);
            }
        }
    }

    float inv0 = 1.0f / l0, inv1 = 1.0f / l1;
    float* Op = O + base;
    int c2 = (lane & 3) * 2;
#pragma unroll
    for (int nt = 0; nt < 8; ++nt) {
        *reinterpret_cast<float2*>(Op + (size_t)row0 * DM + nt * 8 + c2) =
            make_float2(o[nt][0] * inv0, o[nt][1] * inv0);
        *reinterpret_cast<float2*>(Op + (size_t)(row0 + 8) * DM + nt * 8 + c2) =
            make_float2(o[nt][2] * inv1, o[nt][3] * inv1);
    }
}

// ============================================================
// launch — ordered so ncu (-s 5 -c 1) profiles gemm_qkv (#6)
// ============================================================
extern "C" void kernel_launch(void* const* d_in, const int* in_sizes, int n_in,
                              void* d_out, int out_size) {
    const float* x  = (const float*)d_in[0];
    const float* Wq = (const float*)d_in[1];
    const float* Wk = (const float*)d_in[2];
    const float* Wv = (const float*)d_in[3];
    const float* Wo = (const float*)d_in[4];
    float* out = (float*)d_out;

    float *q, *k, *v;
    cudaGetSymbolAddress((void**)&q,  g_q);
    cudaGetSymbolAddress((void**)&k,  g_k);
    cudaGetSymbolAddress((void**)&v,  g_v);

    __nv_bfloat16 *xh, *xl, *aoh, *aol, *wh, *wl;
    __nv_bfloat16 *qh, *ql, *kh, *kl, *vh, *vl;
    cudaGetSymbolAddress((void**)&xh,  g_xh);
    cudaGetSymbolAddress((void**)&xl,  g_xl);
    cudaGetSymbolAddress((void**)&aoh, g_aoh);
    cudaGetSymbolAddress((void**)&aol, g_aol);
    cudaGetSymbolAddress((void**)&wh,  g_wh);
    cudaGetSymbolAddress((void**)&wl,  g_wl);
    cudaGetSymbolAddress((void**)&qh,  g_qh);
    cudaGetSymbolAddress((void**)&ql,  g_ql);
    cudaGetSymbolAddress((void**)&kh,  g_kh);
    cudaGetSymbolAddress((void**)&kl,  g_kl);
    cudaGetSymbolAddress((void**)&vh,  g_vh);
    cudaGetSymbolAddress((void**)&vl,  g_vl);

    cudaFuncSetAttribute(gemm_qkv,  cudaFuncAttributeMaxDynamicSharedMemorySize, GM_SMEM);
    cudaFuncSetAttribute(gemm_mma,  cudaFuncAttributeMaxDynamicSharedMemorySize, GM_SMEM);
    cudaFuncSetAttribute(flash_mma, cudaFuncAttributeMaxDynamicSharedMemorySize, FA_SMEM);

    int nx4 = MROWS * DM / 4;
    int nw4 = DM * DM / 4;

    // launches #1-#5
    rope_table_kernel<<<(TT * HALF_HD + 255) / 256, 256>>>();
    split_kernel<<<(nx4 + 255) / 256, 256>>>(x, xh, xl, nx4);
    split_kernel<<<(nw4 + 255) / 256, 256>>>(Wq, wh + 0 * (size_t)DM * DM, wl + 0 * (size_t)DM * DM, nw4);
    split_kernel<<<(nw4 + 255) / 256, 256>>>(Wk, wh + 1 * (size_t)DM * DM, wl + 1 * (size_t)DM * DM, nw4);
    split_kernel<<<(nw4 + 255) / 256, 256>>>(Wv, wh + 2 * (size_t)DM * DM, wl + 2 * (size_t)DM * DM, nw4);

    // launch #6 — profiled by ncu (-s 5 -c 1)
    gemm_qkv<<<dim3(DM / 128, MROWS / 128, 3), 256, GM_SMEM>>>(
        xh, xl, wh, wl, q, k, v);

    rope_split_kernel<<<(BB * TT * NH * HALF_HD + 255) / 256, 256>>>(q, k, qh, ql, kh, kl);
    split_kernel<<<(nx4 + 255) / 256, 256>>>(v, vh, vl, nx4);
    split_kernel<<<(nw4 + 255) / 256, 256>>>(Wo, wh + 3 * (size_t)DM * DM, wl + 3 * (size_t)DM * DM, nw4);

    flash_mma<<<dim3(TT / 128, BB * NH), 256, FA_SMEM>>>(qh, ql, kh, kl, vh, vl, q);

    split_kernel<<<(nx4 + 255) / 256, 256>>>(q, aoh, aol, nx4);
    gemm_mma<<<dim3(DM / 128, MROWS / 128), 256, GM_SMEM>>>(
        aoh, aol, wh + 3 * (size_t)DM * DM, wl + 3 * (size_t)DM * DM, out, MROWS, DM, DM);
}

// round 14
// speedup vs baseline: 1.5192x; 1.0150x over previous
#include <cuda_runtime.h>
#include <cuda_bf16.h>
#include <stdint.h>
#include <math.h>

#define BB 4
#define TT 2048
#define DM 1024
#define NH 16
#define HD 64
#define MROWS (BB*TT)          // 8192
#define HALF_HD (HD/2)         // 32

// -------- scratch (no cudaMalloc allowed) --------
__device__ float g_q[MROWS*DM];
__device__ float g_k[MROWS*DM];
__device__ float g_v[MROWS*DM];
__device__ float g_cos[TT*HALF_HD];
__device__ float g_sin[TT*HALF_HD];

// bf16 split operands
__device__ __nv_bfloat16 g_xh[MROWS*DM];
__device__ __nv_bfloat16 g_xl[MROWS*DM];
__device__ __nv_bfloat16 g_aoh[MROWS*DM];
__device__ __nv_bfloat16 g_aol[MROWS*DM];
__device__ __nv_bfloat16 g_wh[4][DM*DM];
__device__ __nv_bfloat16 g_wl[4][DM*DM];
// attention operands (post-rope)
__device__ __nv_bfloat16 g_qh[MROWS*DM];
__device__ __nv_bfloat16 g_ql[MROWS*DM];
__device__ __nv_bfloat16 g_kh[MROWS*DM];
__device__ __nv_bfloat16 g_kl[MROWS*DM];
__device__ __nv_bfloat16 g_vh[MROWS*DM];
__device__ __nv_bfloat16 g_vl[MROWS*DM];

// ============================================================
// helpers
// ============================================================
__device__ __forceinline__ uint32_t smem_u32(const void* p) {
    uint32_t a;
    asm("{ .reg .u64 t; cvta.to.shared.u64 t, %1; cvt.u32.u64 %0, t; }"
        : "=r"(a) : "l"(p));
    return a;
}

__device__ __forceinline__ void ldm4(uint32_t r[4], uint32_t addr) {
    asm volatile("ldmatrix.sync.aligned.m8n8.x4.shared.b16 {%0,%1,%2,%3}, [%4];"
                 : "=r"(r[0]), "=r"(r[1]), "=r"(r[2]), "=r"(r[3]) : "r"(addr));
}
__device__ __forceinline__ void ldm4t(uint32_t r[4], uint32_t addr) {
    asm volatile("ldmatrix.sync.aligned.m8n8.x4.trans.shared.b16 {%0,%1,%2,%3}, [%4];"
                 : "=r"(r[0]), "=r"(r[1]), "=r"(r[2]), "=r"(r[3]) : "r"(addr));
}

__device__ __forceinline__ void mma16816(float c[4], const uint32_t a[4], const uint32_t b[2]) {
    asm volatile("mma.sync.aligned.m16n8k16.row.col.f32.bf16.bf16.f32 "
                 "{%0,%1,%2,%3}, {%4,%5,%6,%7}, {%8,%9}, {%0,%1,%2,%3};"
                 : "+f"(c[0]), "+f"(c[1]), "+f"(c[2]), "+f"(c[3])
                 : "r"(a[0]), "r"(a[1]), "r"(a[2]), "r"(a[3]), "r"(b[0]), "r"(b[1]));
}

__device__ __forceinline__ void cp16(uint32_t s, const void* g) {
    asm volatile("cp.async.cg.shared.global [%0], [%1], 16;" :: "r"(s), "l"(g));
}

// 32-col (64B row) tile swizzle — gemm tiles (proven)
__device__ __forceinline__ uint32_t swz_off(int row, int chunk) {
    return (uint32_t)(row * 64 + ((chunk ^ (row & 3) ^ ((row >> 2) & 3)) << 4));
}
// 64-col (128B row) tile swizzle — attention tiles (proven)
__device__ __forceinline__ uint32_t swz64(int row, int chunk) {
    return (uint32_t)(row * 128 + (((chunk ^ (row & 7)) & 7) << 4));
}

__device__ __forceinline__ void tile_cp(uint32_t sbase, const __nv_bfloat16* __restrict__ src,
                                        int row0, int K, int kc, int tid) {
#pragma unroll
    for (int it = 0; it < 2; ++it) {
        int idx = tid + it * 256;
        int r = idx >> 2, c = idx & 3;
        uint32_t soff = sbase + swz_off(r, c);
        const void* g = src + (size_t)(row0 + r) * K + kc + c * 8;
        cp16(soff, g);
    }
}

// pack two fp32 -> bf16x2 hi and residual-lo regs
__device__ __forceinline__ void splitpack(float p0, float p1, uint32_t& h, uint32_t& l) {
    __nv_bfloat16 h0 = __float2bfloat16(p0);
    __nv_bfloat16 h1 = __float2bfloat16(p1);
    __nv_bfloat16 l0 = __float2bfloat16(p0 - __bfloat162float(h0));
    __nv_bfloat16 l1 = __float2bfloat16(p1 - __bfloat162float(h1));
    __nv_bfloat162 hh(h0, h1), ll(l0, l1);
    h = *reinterpret_cast<uint32_t*>(&hh);
    l = *reinterpret_cast<uint32_t*>(&ll);
}

// ============================================================
// fp32 -> bf16 hi/lo split (body shared by split kernels)
// ============================================================
__device__ __forceinline__ void split_body(const float* __restrict__ src,
                                           __nv_bfloat16* __restrict__ hi,
                                           __nv_bfloat16* __restrict__ lo, int i) {
    float4 x = reinterpret_cast<const float4*>(src)[i];
    __nv_bfloat16 h0 = __float2bfloat16(x.x);
    __nv_bfloat16 h1 = __float2bfloat16(x.y);
    __nv_bfloat16 h2 = __float2bfloat16(x.z);
    __nv_bfloat16 h3 = __float2bfloat16(x.w);
    __nv_bfloat16 l0 = __float2bfloat16(x.x - __bfloat162float(h0));
    __nv_bfloat16 l1 = __float2bfloat16(x.y - __bfloat162float(h1));
    __nv_bfloat16 l2 = __float2bfloat16(x.z - __bfloat162float(h2));
    __nv_bfloat16 l3 = __float2bfloat16(x.w - __bfloat162float(h3));
    __nv_bfloat162* hp = reinterpret_cast<__nv_bfloat162*>(hi);
    __nv_bfloat162* lp = reinterpret_cast<__nv_bfloat162*>(lo);
    hp[2*i]   = __nv_bfloat162(h0, h1);
    hp[2*i+1] = __nv_bfloat162(h2, h3);
    lp[2*i]   = __nv_bfloat162(l0, l1);
    lp[2*i+1] = __nv_bfloat162(l2, l3);
}

__global__ void split_kernel(const float* __restrict__ src,
                             __nv_bfloat16* __restrict__ hi,
                             __nv_bfloat16* __restrict__ lo, int n4) {
    int i = blockIdx.x * blockDim.x + threadIdx.x;
    if (i >= n4) return;
    split_body(src, hi, lo, i);
}

// fused split for x + 4 weights (one launch)
#define X_N4 (MROWS*DM/4)      // 2097152
#define W_N4 (DM*DM/4)         // 262144 = 2^18
__global__ void split_all(
    const float* __restrict__ x,
    const float* __restrict__ Wq, const float* __restrict__ Wk,
    const float* __restrict__ Wv, const float* __restrict__ Wo,
    __nv_bfloat16* __restrict__ xh, __nv_bfloat16* __restrict__ xl,
    __nv_bfloat16* __restrict__ wh, __nv_bfloat16* __restrict__ wl)
{
    int i = blockIdx.x * blockDim.x + threadIdx.x;
    if (i < X_N4) {
        split_body(x, xh, xl, i);
    } else {
        int j = i - X_N4;
        int w = j >> 18;
        int off = j & (W_N4 - 1);
        const float* src = (w == 0) ? Wq : (w == 1) ? Wk : (w == 2) ? Wv : Wo;
        split_body(src, wh + (size_t)w * DM * DM, wl + (size_t)w * DM * DM, off);
    }
}

// ============================================================
// GEMM mainloop core — 3-stage cp.async pipeline, one barrier
// per K-chunk (round-13 proven-safe structure)
// ============================================================
#define GM_SMEM (3*32768)

__device__ __forceinline__ void load_chunk(
    uint32_t buf, const __nv_bfloat16* Ah, const __nv_bfloat16* Al,
    const __nv_bfloat16* Bh, const __nv_bfloat16* Bl,
    int m0, int n0, int K, int kc, int tid)
{
    tile_cp(buf +     0, Ah, m0, K, kc, tid);
    tile_cp(buf +  8192, Al, m0, K, kc, tid);
    tile_cp(buf + 16384, Bh, n0, K, kc, tid);
    tile_cp(buf + 24576, Bl, n0, K, kc, tid);
    asm volatile("cp.async.commit_group;");
}

__device__ __forceinline__ void gemm_core(
    uint32_t sb, const __nv_bfloat16* Ah, const __nv_bfloat16* Al,
    const __nv_bfloat16* Bh, const __nv_bfloat16* Bl,
    int m0, int n0, int K, int tid, int lane,
    int wm, int wn, float acc[4][4][4])
{
    const int nch = K / 32;

    load_chunk(sb,          Ah, Al, Bh, Bl, m0, n0, K,  0, tid);
    load_chunk(sb + 32768,  Ah, Al, Bh, Bl, m0, n0, K, 32, tid);

    for (int ch = 0; ch < nch; ++ch) {
        if (ch + 1 < nch) {
            asm volatile("cp.async.wait_group 1;");
        } else {
            asm volatile("cp.async.wait_group 0;");
        }
        __syncthreads();

        if (ch + 2 < nch) {
            uint32_t nb = sb + (uint32_t)(((ch + 2) % 3) * 32768);
            load_chunk(nb, Ah, Al, Bh, Bl, m0, n0, K, (ch + 2) * 32, tid);
        }

        uint32_t bufA_h = sb + (uint32_t)((ch % 3) * 32768);
        uint32_t bufA_l = bufA_h + 8192;
        uint32_t bufB_h = bufA_h + 16384;
        uint32_t bufB_l = bufA_h + 24576;

#pragma unroll
        for (int ks = 0; ks < 2; ++ks) {
            uint32_t ah[4][4], al[4][4], bh[4][2], bl[4][2];

            int ra  = ((lane >> 3) & 1) * 8 + (lane & 7);
            int caf = (lane >> 4) & 1;
#pragma unroll
            for (int mt = 0; mt < 4; ++mt) {
                int row = wm + mt * 16 + ra;
                uint32_t off = swz_off(row, ks * 2 + caf);
                ldm4(ah[mt], bufA_h + off);
                ldm4(al[mt], bufA_l + off);
            }

            int rb  = ((lane >> 4) & 1) * 8 + (lane & 7);
            int cbf = (lane >> 3) & 1;
#pragma unroll
            for (int p = 0; p < 2; ++p) {
                int row = wn + p * 16 + rb;
                uint32_t off = swz_off(row, ks * 2 + cbf);
                uint32_t t[4];
                ldm4(t, bufB_h + off);
                bh[p*2][0] = t[0]; bh[p*2][1] = t[1];
                bh[p*2+1][0] = t[2]; bh[p*2+1][1] = t[3];
                ldm4(t, bufB_l + off);
                bl[p*2][0] = t[0]; bl[p*2][1] = t[1];
                bl[p*2+1][0] = t[2]; bl[p*2+1][1] = t[3];
            }

#pragma unroll
            for (int mt = 0; mt < 4; ++mt)
#pragma unroll
                for (int nt = 0; nt < 4; ++nt) {
                    mma16816(acc[mt][nt], ah[mt], bh[nt]);
                    mma16816(acc[mt][nt], ah[mt], bl[nt]);
                    mma16816(acc[mt][nt], al[mt], bh[nt]);
                }
        }
    }
    __syncthreads();
}

// ============================================================
// Fused QKV GEMM — 2 CTAs/SM target (regs <= 128)
// ============================================================
__global__ void __launch_bounds__(256, 2) gemm_qkv(
    const __nv_bfloat16* __restrict__ xh, const __nv_bfloat16* __restrict__ xl,
    const __nv_bfloat16* __restrict__ wh, const __nv_bfloat16* __restrict__ wl,
    float* __restrict__ q, float* __restrict__ k, float* __restrict__ v)
{
    extern __shared__ char smem[];
    uint32_t sb = smem_u32(smem);
    int tid = threadIdx.x, lane = tid & 31, wid = tid >> 5;
    int m0 = blockIdx.y * 128, n0 = blockIdx.x * 128;
    int wm = (wid & 1) * 64, wn = (wid >> 1) * 32;
    int z = blockIdx.z;

    const __nv_bfloat16* Bh = wh + (size_t)z * DM * DM;
    const __nv_bfloat16* Bl = wl + (size_t)z * DM * DM;
    float* C = (z == 0) ? q : (z == 1) ? k : v;

    float acc[4][4][4];
#pragma unroll
    for (int a = 0; a < 4; a++)
#pragma unroll
        for (int b = 0; b < 4; b++)
#pragma unroll
            for (int c = 0; c < 4; c++) acc[a][b][c] = 0.0f;

    gemm_core(sb, xh, xl, Bh, Bl, m0, n0, DM, tid, lane, wm, wn, acc);

    int g = lane >> 2, c2 = (lane & 3) * 2;
#pragma unroll
    for (int mt = 0; mt < 4; ++mt)
#pragma unroll
        for (int nt = 0; nt < 4; ++nt) {
            int row = m0 + wm + mt * 16 + g;
            int col = n0 + wn + nt * 8 + c2;
            *reinterpret_cast<float2*>(C + (size_t)row * DM + col) =
                make_float2(acc[mt][nt][0], acc[mt][nt][1]);
            *reinterpret_cast<float2*>(C + (size_t)(row + 8) * DM + col) =
                make_float2(acc[mt][nt][2], acc[mt][nt][3]);
        }
}

// ============================================================
// Generic GEMM (fp32 out) — Wo projection, 2 CTAs/SM target
// ============================================================
__global__ void __launch_bounds__(256, 2) gemm_mma(
    const __nv_bfloat16* __restrict__ Ah, const __nv_bfloat16* __restrict__ Al,
    const __nv_bfloat16* __restrict__ Bh, const __nv_bfloat16* __restrict__ Bl,
    float* __restrict__ C, int M, int N, int K)
{
    extern __shared__ char smem[];
    uint32_t sb = smem_u32(smem);
    int tid = threadIdx.x, lane = tid & 31, wid = tid >> 5;
    int m0 = blockIdx.y * 128, n0 = blockIdx.x * 128;
    int wm = (wid & 1) * 64, wn = (wid >> 1) * 32;

    float acc[4][4][4];
#pragma unroll
    for (int a = 0; a < 4; a++)
#pragma unroll
        for (int b = 0; b < 4; b++)
#pragma unroll
            for (int c = 0; c < 4; c++) acc[a][b][c] = 0.0f;

    gemm_core(sb, Ah, Al, Bh, Bl, m0, n0, K, tid, lane, wm, wn, acc);

    int g = lane >> 2, c2 = (lane & 3) * 2;
#pragma unroll
    for (int mt = 0; mt < 4; ++mt)
#pragma unroll
        for (int nt = 0; nt < 4; ++nt) {
            int row = m0 + wm + mt * 16 + g;
            int col = n0 + wn + nt * 8 + c2;
            *reinterpret_cast<float2*>(C + (size_t)row * N + col) =
                make_float2(acc[mt][nt][0], acc[mt][nt][1]);
            *reinterpret_cast<float2*>(C + (size_t)(row + 8) * N + col) =
                make_float2(acc[mt][nt][2], acc[mt][nt][3]);
        }
}

// ============================================================
// RoPE sin/cos table (fp64)
// ============================================================
__global__ void rope_table_kernel() {
    int i = blockIdx.x * blockDim.x + threadIdx.x;
    if (i >= TT * HALF_HD) return;
    int t = i / HALF_HD;
    int f = i % HALF_HD;
    double inv = exp(-((double)f / (double)HALF_HD) * log(10000.0));
    double ang = (double)t * inv;
    g_cos[i] = (float)cos(ang);
    g_sin[i] = (float)sin(ang);
}

// ============================================================
// RoPE + bf16 hi/lo split for Q,K (fused; fp32 in, bf16 out)
// ============================================================
__global__ void rope_split_kernel(const float* __restrict__ q, const float* __restrict__ k,
                                  __nv_bfloat16* __restrict__ qh, __nv_bfloat16* __restrict__ ql,
                                  __nv_bfloat16* __restrict__ kh, __nv_bfloat16* __restrict__ kl) {
    int i = blockIdx.x * blockDim.x + threadIdx.x;
    if (i >= BB * TT * NH * HALF_HD) return;
    int f    = i & (HALF_HD - 1);
    int rest = i >> 5;
    int h    = rest & (NH - 1);
    int bt   = rest >> 4;
    int t    = bt & (TT - 1);
    int off  = bt * DM + h * HD + f;
    float c = g_cos[t * HALF_HD + f];
    float s = g_sin[t * HALF_HD + f];

    float q1 = q[off], q2 = q[off + HALF_HD];
    float qa = q1 * c - q2 * s;
    float qb = q2 * c + q1 * s;
    __nv_bfloat16 ha = __float2bfloat16(qa);
    __nv_bfloat16 hb = __float2bfloat16(qb);
    qh[off] = ha;  qh[off + HALF_HD] = hb;
    ql[off] = __float2bfloat16(qa - __bfloat162float(ha));
    ql[off + HALF_HD] = __float2bfloat16(qb - __bfloat162float(hb));

    float k1 = k[off], k2 = k[off + HALF_HD];
    float ka = k1 * c - k2 * s;
    float kb = k2 * c + k1 * s;
    ha = __float2bfloat16(ka);
    hb = __float2bfloat16(kb);
    kh[off] = ha;  kh[off + HALF_HD] = hb;
    kl[off] = __float2bfloat16(ka - __bfloat162float(ha));
    kl[off + HALF_HD] = __float2bfloat16(kb - __bfloat162float(hb));
}

// ============================================================
// Tensor-core flash attention (causal, FA2-style, bf16x3)
// ============================================================
#define FA_SMEM 98304
#define FQH 0
#define FQL 16384
#define FKH 0
#define FKL 8192
#define FVH 16384
#define FVL 24576

__global__ void __launch_bounds__(256) flash_mma(
    const __nv_bfloat16* __restrict__ qh, const __nv_bfloat16* __restrict__ ql,
    const __nv_bfloat16* __restrict__ kh, const __nv_bfloat16* __restrict__ kl,
    const __nv_bfloat16* __restrict__ vh, const __nv_bfloat16* __restrict__ vl,
    float* __restrict__ O)
{
    extern __shared__ char smem[];
    uint32_t sb = smem_u32(smem);
    int tid = threadIdx.x, lane = tid & 31, w = tid >> 5;

    int qt = (int)gridDim.x - 1 - (int)blockIdx.x;
    int bh_ = blockIdx.y;
    int b = bh_ >> 4, h = bh_ & 15;
    size_t base = (size_t)b * TT * DM + h * HD;
    int q0 = qt * 128;

    const __nv_bfloat16* Qh = qh + base;
    const __nv_bfloat16* Ql = ql + base;
    const __nv_bfloat16* Kh = kh + base;
    const __nv_bfloat16* Kl = kl + base;
    const __nv_bfloat16* Vh = vh + base;
    const __nv_bfloat16* Vl = vl + base;

    for (int i = tid; i < 1024; i += 256) {
        int r = i >> 3, c = i & 7;
        size_t g = (size_t)(q0 + r) * DM + c * 8;
        cp16(sb + FQH + swz64(r, c), Qh + g);
        cp16(sb + FQL + swz64(r, c), Ql + g);
    }
    {
        uint32_t buf = sb + 32768;
        for (int i = tid; i < 512; i += 256) {
            int r = i >> 3, c = i & 7;
            size_t g = (size_t)r * DM + c * 8;
            uint32_t so = swz64(r, c);
            cp16(buf + FKH + so, Kh + g);
            cp16(buf + FKL + so, Kl + g);
            cp16(buf + FVH + so, Vh + g);
            cp16(buf + FVL + so, Vl + g);
        }
    }
    asm volatile("cp.async.commit_group;");

    const float NEG_INF = -__int_as_float(0x7f800000);
    float m0 = NEG_INF, m1 = NEG_INF, l0 = 0.0f, l1 = 0.0f;
    float o[8][4];
#pragma unroll
    for (int nt = 0; nt < 8; nt++)
#pragma unroll
        for (int c = 0; c < 4; c++) o[nt][c] = 0.0f;

    int nkt = 2 * qt + 2;
    int row0 = q0 + w * 16 + (lane >> 2);

    for (int kt = 0; kt < nkt; kt++) {
        uint32_t cur = sb + 32768u + (uint32_t)((kt & 1) * 32768);
        if (kt + 1 < nkt) {
            __syncthreads();
            uint32_t nb = sb + 32768u + (uint32_t)(((kt + 1) & 1) * 32768);
            int k0n = (kt + 1) * 64;
            for (int i = tid; i < 512; i += 256) {
                int r = i >> 3, c = i & 7;
                size_t g = (size_t)(k0n + r) * DM + c * 8;
                uint32_t so = swz64(r, c);
                cp16(nb + FKH + so, Kh + g);
                cp16(nb + FKL + so, Kl + g);
                cp16(nb + FVH + so, Vh + g);
                cp16(nb + FVL + so, Vl + g);
            }
            asm volatile("cp.async.commit_group;");
            asm volatile("cp.async.wait_group 1;");
        } else {
            asm volatile("cp.async.wait_group 0;");
        }
        __syncthreads();

        int k0 = kt * 64;

        float s[8][4];
#pragma unroll
        for (int nt = 0; nt < 8; nt++)
#pragma unroll
            for (int c = 0; c < 4; c++) s[nt][c] = 0.0f;

        int ra  = ((lane >> 3) & 1) * 8 + (lane & 7);
        int caf = (lane >> 4) & 1;
        int rb  = ((lane >> 4) & 1) * 8 + (lane & 7);
        int cbf = (lane >> 3) & 1;

#pragma unroll
        for (int ks = 0; ks < 4; ++ks) {
            uint32_t aH[4], aL[4];
            uint32_t qoff = swz64(w * 16 + ra, ks * 2 + caf);
            ldm4(aH, sb + FQH + qoff);
            ldm4(aL, sb + FQL + qoff);

            uint32_t bH[8][2], bL[8][2];
#pragma unroll
            for (int p = 0; p < 4; ++p) {
                uint32_t off = swz64(p * 16 + rb, ks * 2 + cbf);
                uint32_t t[4];
                ldm4(t, cur + FKH + off);
                bH[p*2][0] = t[0]; bH[p*2][1] = t[1];
                bH[p*2+1][0] = t[2]; bH[p*2+1][1] = t[3];
                ldm4(t, cur + FKL + off);
                bL[p*2][0] = t[0]; bL[p*2][1] = t[1];
                bL[p*2+1][0] = t[2]; bL[p*2+1][1] = t[3];
            }
#pragma unroll
            for (int nt = 0; nt < 8; ++nt) {
                mma16816(s[nt], aH, bH[nt]);
                mma16816(s[nt], aH, bL[nt]);
                mma16816(s[nt], aL, bH[nt]);
            }
        }

        bool needmask = (k0 + 63 > q0);
#pragma unroll
        for (int nt = 0; nt < 8; ++nt) {
#pragma unroll
            for (int c = 0; c < 4; ++c) {
                float v = s[nt][c] * 0.125f;
                if (needmask) {
                    int col = k0 + nt * 8 + (lane & 3) * 2 + (c & 1);
                    int rowg = row0 + ((c >> 1) << 3);
                    if (col > rowg) v = NEG_INF;
                }
                s[nt][c] = v;
            }
        }

        float mx0 = NEG_INF, mx1 = NEG_INF;
#pragma unroll
        for (int nt = 0; nt < 8; ++nt) {
            mx0 = fmaxf(mx0, fmaxf(s[nt][0], s[nt][1]));
            mx1 = fmaxf(mx1, fmaxf(s[nt][2], s[nt][3]));
        }
        mx0 = fmaxf(mx0, __shfl_xor_sync(0xffffffffu, mx0, 1));
        mx0 = fmaxf(mx0, __shfl_xor_sync(0xffffffffu, mx0, 2));
        mx1 = fmaxf(mx1, __shfl_xor_sync(0xffffffffu, mx1, 1));
        mx1 = fmaxf(mx1, __shfl_xor_sync(0xffffffffu, mx1, 2));

        float mn0 = fmaxf(m0, mx0), mn1 = fmaxf(m1, mx1);
        float al0 = __expf(m0 - mn0), al1 = __expf(m1 - mn1);
        if (m0 == NEG_INF && mn0 == NEG_INF) al0 = 1.0f;
        if (m1 == NEG_INF && mn1 == NEG_INF) al1 = 1.0f;
        m0 = mn0; m1 = mn1;

        float ls0 = 0.0f, ls1 = 0.0f;
#pragma unroll
        for (int nt = 0; nt < 8; ++nt) {
            float p0 = (s[nt][0] == NEG_INF) ? 0.0f : __expf(s[nt][0] - mn0);
            float p1 = (s[nt][1] == NEG_INF) ? 0.0f : __expf(s[nt][1] - mn0);
            float p2 = (s[nt][2] == NEG_INF) ? 0.0f : __expf(s[nt][2] - mn1);
            float p3 = (s[nt][3] == NEG_INF) ? 0.0f : __expf(s[nt][3] - mn1);
            s[nt][0] = p0; s[nt][1] = p1; s[nt][2] = p2; s[nt][3] = p3;
            ls0 += p0 + p1; ls1 += p2 + p3;
        }
        ls0 += __shfl_xor_sync(0xffffffffu, ls0, 1);
        ls0 += __shfl_xor_sync(0xffffffffu, ls0, 2);
        ls1 += __shfl_xor_sync(0xffffffffu, ls1, 1);
        ls1 += __shfl_xor_sync(0xffffffffu, ls1, 2);
        l0 = l0 * al0 + ls0;
        l1 = l1 * al1 + ls1;

#pragma unroll
        for (int nt = 0; nt < 8; ++nt) {
            o[nt][0] *= al0; o[nt][1] *= al0;
            o[nt][2] *= al1; o[nt][3] *= al1;
        }

#pragma unroll
        for (int ks = 0; ks < 4; ++ks) {
            uint32_t pH[4], pL[4];
            splitpack(s[2*ks][0],   s[2*ks][1],   pH[0], pL[0]);
            splitpack(s[2*ks][2],   s[2*ks][3],   pH[1], pL[1]);
            splitpack(s[2*ks+1][0], s[2*ks+1][1], pH[2], pL[2]);
            splitpack(s[2*ks+1][2], s[2*ks+1][3], pH[3], pL[3]);

            int mm = lane >> 3, la = lane & 7;
            int vrow = ks * 16 + (mm & 1) * 8 + la;
#pragma unroll
            for (int ntp = 0; ntp < 4; ++ntp) {
                int vchunk = ntp * 2 + (mm >> 1);
                uint32_t off = swz64(vrow, vchunk);
                uint32_t tH[4], tL[4];
                ldm4t(tH, cur + FVH + off);
                ldm4t(tL, cur + FVL + off);
                uint32_t b0H[2] = {tH[0], tH[1]}, b1H[2] = {tH[2], tH[3]};
                uint32_t b0L[2] = {tL[0], tL[1]}, b1L[2] = {tL[2], tL[3]};
                mma16816(o[2*ntp],   pH, b0H);
                mma16816(o[2*ntp],   pH, b0L);
                mma16816(o[2*ntp],   pL, b0H);
                mma16816(o[2*ntp+1], pH, b1H);
                mma16816(o[2*ntp+1], pH, b1L);
                mma16816(o[2*ntp+1], pL, b1H);
            }
        }
    }

    float inv0 = 1.0f / l0, inv1 = 1.0f / l1;
    float* Op = O + base;
    int c2 = (lane & 3) * 2;
#pragma unroll
    for (int nt = 0; nt < 8; ++nt) {
        *reinterpret_cast<float2*>(Op + (size_t)row0 * DM + nt * 8 + c2) =
            make_float2(o[nt][0] * inv0, o[nt][1] * inv0);
        *reinterpret_cast<float2*>(Op + (size_t)(row0 + 8) * DM + nt * 8 + c2) =
            make_float2(o[nt][2] * inv1, o[nt][3] * inv1);
    }
}

// ============================================================
// launch — ordered so ncu (-s 5 -c 1) profiles flash_mma (#6)
// ============================================================
extern "C" void kernel_launch(void* const* d_in, const int* in_sizes, int n_in,
                              void* d_out, int out_size) {
    const float* x  = (const float*)d_in[0];
    const float* Wq = (const float*)d_in[1];
    const float* Wk = (const float*)d_in[2];
    const float* Wv = (const float*)d_in[3];
    const float* Wo = (const float*)d_in[4];
    float* out = (float*)d_out;

    float *q, *k, *v;
    cudaGetSymbolAddress((void**)&q,  g_q);
    cudaGetSymbolAddress((void**)&k,  g_k);
    cudaGetSymbolAddress((void**)&v,  g_v);

    __nv_bfloat16 *xh, *xl, *aoh, *aol, *wh, *wl;
    __nv_bfloat16 *qh, *ql, *kh, *kl, *vh, *vl;
    cudaGetSymbolAddress((void**)&xh,  g_xh);
    cudaGetSymbolAddress((void**)&xl,  g_xl);
    cudaGetSymbolAddress((void**)&aoh, g_aoh);
    cudaGetSymbolAddress((void**)&aol, g_aol);
    cudaGetSymbolAddress((void**)&wh,  g_wh);
    cudaGetSymbolAddress((void**)&wl,  g_wl);
    cudaGetSymbolAddress((void**)&qh,  g_qh);
    cudaGetSymbolAddress((void**)&ql,  g_ql);
    cudaGetSymbolAddress((void**)&kh,  g_kh);
    cudaGetSymbolAddress((void**)&kl,  g_kl);
    cudaGetSymbolAddress((void**)&vh,  g_vh);
    cudaGetSymbolAddress((void**)&vl,  g_vl);

    cudaFuncSetAttribute(gemm_qkv,  cudaFuncAttributeMaxDynamicSharedMemorySize, GM_SMEM);
    cudaFuncSetAttribute(gemm_mma,  cudaFuncAttributeMaxDynamicSharedMemorySize, GM_SMEM);
    cudaFuncSetAttribute(flash_mma, cudaFuncAttributeMaxDynamicSharedMemorySize, FA_SMEM);

    int nx4 = MROWS * DM / 4;

    // #1
    rope_table_kernel<<<(TT * HALF_HD + 255) / 256, 256>>>();
    // #2 — fused x + 4 weight splits
    split_all<<<(X_N4 + 4 * W_N4 + 255) / 256, 256>>>(
        x, Wq, Wk, Wv, Wo, xh, xl, wh, wl);
    // #3 — fused QKV projections (2 CTAs/SM)
    gemm_qkv<<<dim3(DM / 128, MROWS / 128, 3), 256, GM_SMEM>>>(
        xh, xl, wh, wl, q, k, v);
    // #4
    rope_split_kernel<<<(BB * TT * NH * HALF_HD + 255) / 256, 256>>>(q, k, qh, ql, kh, kl);
    // #5
    split_kernel<<<(nx4 + 255) / 256, 256>>>(v, vh, vl, nx4);
    // #6 — profiled by ncu (-s 5 -c 1)
    flash_mma<<<dim3(TT / 128, BB * NH), 256, FA_SMEM>>>(qh, ql, kh, kl, vh, vl, q);
    // #7
    split_kernel<<<(nx4 + 255) / 256, 256>>>(q, aoh, aol, nx4);
    // #8
    gemm_mma<<<dim3(DM / 128, MROWS / 128), 256, GM_SMEM>>>(
        aoh, aol, wh + 3 * (size_t)DM * DM, wl + 3 * (size_t)DM * DM, out, MROWS, DM, DM);
}

// round 15
// speedup vs baseline: 1.5304x; 1.0074x over previous
#include <cuda_runtime.h>
#include <cuda_bf16.h>
#include <stdint.h>
#include <math.h>

#define BB 4
#define TT 2048
#define DM 1024
#define NH 16
#define HD 64
#define MROWS (BB*TT)          // 8192
#define HALF_HD (HD/2)         // 32

// -------- scratch (no cudaMalloc allowed) --------
__device__ float g_q[MROWS*DM];
__device__ float g_k[MROWS*DM];
__device__ float g_v[MROWS*DM];
__device__ float g_cos[TT*HALF_HD];
__device__ float g_sin[TT*HALF_HD];

// bf16 split operands
__device__ __nv_bfloat16 g_xh[MROWS*DM];
__device__ __nv_bfloat16 g_xl[MROWS*DM];
__device__ __nv_bfloat16 g_aoh[MROWS*DM];
__device__ __nv_bfloat16 g_aol[MROWS*DM];
__device__ __nv_bfloat16 g_wh[4][DM*DM];
__device__ __nv_bfloat16 g_wl[4][DM*DM];
// attention operands (post-rope)
__device__ __nv_bfloat16 g_qh[MROWS*DM];
__device__ __nv_bfloat16 g_ql[MROWS*DM];
__device__ __nv_bfloat16 g_kh[MROWS*DM];
__device__ __nv_bfloat16 g_kl[MROWS*DM];
__device__ __nv_bfloat16 g_vh[MROWS*DM];
__device__ __nv_bfloat16 g_vl[MROWS*DM];

// ============================================================
// helpers
// ============================================================
__device__ __forceinline__ uint32_t smem_u32(const void* p) {
    uint32_t a;
    asm("{ .reg .u64 t; cvta.to.shared.u64 t, %1; cvt.u32.u64 %0, t; }"
        : "=r"(a) : "l"(p));
    return a;
}

__device__ __forceinline__ void ldm4(uint32_t r[4], uint32_t addr) {
    asm volatile("ldmatrix.sync.aligned.m8n8.x4.shared.b16 {%0,%1,%2,%3}, [%4];"
                 : "=r"(r[0]), "=r"(r[1]), "=r"(r[2]), "=r"(r[3]) : "r"(addr));
}
__device__ __forceinline__ void ldm4t(uint32_t r[4], uint32_t addr) {
    asm volatile("ldmatrix.sync.aligned.m8n8.x4.trans.shared.b16 {%0,%1,%2,%3}, [%4];"
                 : "=r"(r[0]), "=r"(r[1]), "=r"(r[2]), "=r"(r[3]) : "r"(addr));
}

__device__ __forceinline__ void mma16816(float c[4], const uint32_t a[4], const uint32_t b[2]) {
    asm volatile("mma.sync.aligned.m16n8k16.row.col.f32.bf16.bf16.f32 "
                 "{%0,%1,%2,%3}, {%4,%5,%6,%7}, {%8,%9}, {%0,%1,%2,%3};"
                 : "+f"(c[0]), "+f"(c[1]), "+f"(c[2]), "+f"(c[3])
                 : "r"(a[0]), "r"(a[1]), "r"(a[2]), "r"(a[3]), "r"(b[0]), "r"(b[1]));
}

__device__ __forceinline__ void cp16(uint32_t s, const void* g) {
    asm volatile("cp.async.cg.shared.global [%0], [%1], 16;" :: "r"(s), "l"(g));
}

// 32-col (64B row) tile swizzle — gemm tiles (proven)
__device__ __forceinline__ uint32_t swz_off(int row, int chunk) {
    return (uint32_t)(row * 64 + ((chunk ^ (row & 3) ^ ((row >> 2) & 3)) << 4));
}
// 64-col (128B row) tile swizzle — attention tiles (proven)
__device__ __forceinline__ uint32_t swz64(int row, int chunk) {
    return (uint32_t)(row * 128 + (((chunk ^ (row & 7)) & 7) << 4));
}

__device__ __forceinline__ void tile_cp(uint32_t sbase, const __nv_bfloat16* __restrict__ src,
                                        int row0, int K, int kc, int tid) {
#pragma unroll
    for (int it = 0; it < 2; ++it) {
        int idx = tid + it * 256;
        int r = idx >> 2, c = idx & 3;
        uint32_t soff = sbase + swz_off(r, c);
        const void* g = src + (size_t)(row0 + r) * K + kc + c * 8;
        cp16(soff, g);
    }
}

// pack two fp32 -> bf16x2 hi and residual-lo regs
__device__ __forceinline__ void splitpack(float p0, float p1, uint32_t& h, uint32_t& l) {
    __nv_bfloat16 h0 = __float2bfloat16(p0);
    __nv_bfloat16 h1 = __float2bfloat16(p1);
    __nv_bfloat16 l0 = __float2bfloat16(p0 - __bfloat162float(h0));
    __nv_bfloat16 l1 = __float2bfloat16(p1 - __bfloat162float(h1));
    __nv_bfloat162 hh(h0, h1), ll(l0, l1);
    h = *reinterpret_cast<uint32_t*>(&hh);
    l = *reinterpret_cast<uint32_t*>(&ll);
}

// ============================================================
// fp32 -> bf16 hi/lo split (body shared)
// ============================================================
__device__ __forceinline__ void split_body(const float* __restrict__ src,
                                           __nv_bfloat16* __restrict__ hi,
                                           __nv_bfloat16* __restrict__ lo, int i) {
    float4 x = reinterpret_cast<const float4*>(src)[i];
    __nv_bfloat16 h0 = __float2bfloat16(x.x);
    __nv_bfloat16 h1 = __float2bfloat16(x.y);
    __nv_bfloat16 h2 = __float2bfloat16(x.z);
    __nv_bfloat16 h3 = __float2bfloat16(x.w);
    __nv_bfloat16 l0 = __float2bfloat16(x.x - __bfloat162float(h0));
    __nv_bfloat16 l1 = __float2bfloat16(x.y - __bfloat162float(h1));
    __nv_bfloat16 l2 = __float2bfloat16(x.z - __bfloat162float(h2));
    __nv_bfloat16 l3 = __float2bfloat16(x.w - __bfloat162float(h3));
    __nv_bfloat162* hp = reinterpret_cast<__nv_bfloat162*>(hi);
    __nv_bfloat162* lp = reinterpret_cast<__nv_bfloat162*>(lo);
    hp[2*i]   = __nv_bfloat162(h0, h1);
    hp[2*i+1] = __nv_bfloat162(h2, h3);
    lp[2*i]   = __nv_bfloat162(l0, l1);
    lp[2*i+1] = __nv_bfloat162(l2, l3);
}

// fused split for x + 4 weights (one launch)
#define X_N4 (MROWS*DM/4)      // 2097152
#define W_N4 (DM*DM/4)         // 262144 = 2^18
__global__ void split_all(
    const float* __restrict__ x,
    const float* __restrict__ Wq, const float* __restrict__ Wk,
    const float* __restrict__ Wv, const float* __restrict__ Wo,
    __nv_bfloat16* __restrict__ xh, __nv_bfloat16* __restrict__ xl,
    __nv_bfloat16* __restrict__ wh, __nv_bfloat16* __restrict__ wl)
{
    int i = blockIdx.x * blockDim.x + threadIdx.x;
    if (i < X_N4) {
        split_body(x, xh, xl, i);
    } else {
        int j = i - X_N4;
        int w = j >> 18;
        int off = j & (W_N4 - 1);
        const float* src = (w == 0) ? Wq : (w == 1) ? Wk : (w == 2) ? Wv : Wo;
        split_body(src, wh + (size_t)w * DM * DM, wl + (size_t)w * DM * DM, off);
    }
}

// tiny dummy to position gemm_qkv at our launch #4 for ncu (-s 5 = harness+2)
__global__ void dummy_kernel() {}

// ============================================================
// GEMM mainloop core — 3-stage cp.async pipeline, one barrier
// per K-chunk
// ============================================================
#define GM_SMEM (3*32768)

__device__ __forceinline__ void load_chunk(
    uint32_t buf, const __nv_bfloat16* Ah, const __nv_bfloat16* Al,
    const __nv_bfloat16* Bh, const __nv_bfloat16* Bl,
    int m0, int n0, int K, int kc, int tid)
{
    tile_cp(buf +     0, Ah, m0, K, kc, tid);
    tile_cp(buf +  8192, Al, m0, K, kc, tid);
    tile_cp(buf + 16384, Bh, n0, K, kc, tid);
    tile_cp(buf + 24576, Bl, n0, K, kc, tid);
    asm volatile("cp.async.commit_group;");
}

__device__ __forceinline__ void gemm_core(
    uint32_t sb, const __nv_bfloat16* Ah, const __nv_bfloat16* Al,
    const __nv_bfloat16* Bh, const __nv_bfloat16* Bl,
    int m0, int n0, int K, int tid, int lane,
    int wm, int wn, float acc[4][4][4])
{
    const int nch = K / 32;

    load_chunk(sb,          Ah, Al, Bh, Bl, m0, n0, K,  0, tid);
    load_chunk(sb + 32768,  Ah, Al, Bh, Bl, m0, n0, K, 32, tid);

    for (int ch = 0; ch < nch; ++ch) {
        if (ch + 1 < nch) {
            asm volatile("cp.async.wait_group 1;");
        } else {
            asm volatile("cp.async.wait_group 0;");
        }
        __syncthreads();

        if (ch + 2 < nch) {
            uint32_t nb = sb + (uint32_t)(((ch + 2) % 3) * 32768);
            load_chunk(nb, Ah, Al, Bh, Bl, m0, n0, K, (ch + 2) * 32, tid);
        }

        uint32_t bufA_h = sb + (uint32_t)((ch % 3) * 32768);
        uint32_t bufA_l = bufA_h + 8192;
        uint32_t bufB_h = bufA_h + 16384;
        uint32_t bufB_l = bufA_h + 24576;

#pragma unroll
        for (int ks = 0; ks < 2; ++ks) {
            uint32_t ah[4][4], al[4][4], bh[4][2], bl[4][2];

            int ra  = ((lane >> 3) & 1) * 8 + (lane & 7);
            int caf = (lane >> 4) & 1;
#pragma unroll
            for (int mt = 0; mt < 4; ++mt) {
                int row = wm + mt * 16 + ra;
                uint32_t off = swz_off(row, ks * 2 + caf);
                ldm4(ah[mt], bufA_h + off);
                ldm4(al[mt], bufA_l + off);
            }

            int rb  = ((lane >> 4) & 1) * 8 + (lane & 7);
            int cbf = (lane >> 3) & 1;
#pragma unroll
            for (int p = 0; p < 2; ++p) {
                int row = wn + p * 16 + rb;
                uint32_t off = swz_off(row, ks * 2 + cbf);
                uint32_t t[4];
                ldm4(t, bufB_h + off);
                bh[p*2][0] = t[0]; bh[p*2][1] = t[1];
                bh[p*2+1][0] = t[2]; bh[p*2+1][1] = t[3];
                ldm4(t, bufB_l + off);
                bl[p*2][0] = t[0]; bl[p*2][1] = t[1];
                bl[p*2+1][0] = t[2]; bl[p*2+1][1] = t[3];
            }

#pragma unroll
            for (int mt = 0; mt < 4; ++mt)
#pragma unroll
                for (int nt = 0; nt < 4; ++nt) {
                    mma16816(acc[mt][nt], ah[mt], bh[nt]);
                    mma16816(acc[mt][nt], ah[mt], bl[nt]);
                    mma16816(acc[mt][nt], al[mt], bh[nt]);
                }
        }
    }
    __syncthreads();
}

// ============================================================
// Fused QKV GEMM — 2 CTAs/SM target
// ============================================================
__global__ void __launch_bounds__(256, 2) gemm_qkv(
    const __nv_bfloat16* __restrict__ xh, const __nv_bfloat16* __restrict__ xl,
    const __nv_bfloat16* __restrict__ wh, const __nv_bfloat16* __restrict__ wl,
    float* __restrict__ q, float* __restrict__ k, float* __restrict__ v)
{
    extern __shared__ char smem[];
    uint32_t sb = smem_u32(smem);
    int tid = threadIdx.x, lane = tid & 31, wid = tid >> 5;
    int m0 = blockIdx.y * 128, n0 = blockIdx.x * 128;
    int wm = (wid & 1) * 64, wn = (wid >> 1) * 32;
    int z = blockIdx.z;

    const __nv_bfloat16* Bh = wh + (size_t)z * DM * DM;
    const __nv_bfloat16* Bl = wl + (size_t)z * DM * DM;
    float* C = (z == 0) ? q : (z == 1) ? k : v;

    float acc[4][4][4];
#pragma unroll
    for (int a = 0; a < 4; a++)
#pragma unroll
        for (int b = 0; b < 4; b++)
#pragma unroll
            for (int c = 0; c < 4; c++) acc[a][b][c] = 0.0f;

    gemm_core(sb, xh, xl, Bh, Bl, m0, n0, DM, tid, lane, wm, wn, acc);

    int g = lane >> 2, c2 = (lane & 3) * 2;
#pragma unroll
    for (int mt = 0; mt < 4; ++mt)
#pragma unroll
        for (int nt = 0; nt < 4; ++nt) {
            int row = m0 + wm + mt * 16 + g;
            int col = n0 + wn + nt * 8 + c2;
            *reinterpret_cast<float2*>(C + (size_t)row * DM + col) =
                make_float2(acc[mt][nt][0], acc[mt][nt][1]);
            *reinterpret_cast<float2*>(C + (size_t)(row + 8) * DM + col) =
                make_float2(acc[mt][nt][2], acc[mt][nt][3]);
        }
}

// ============================================================
// Generic GEMM (fp32 out) — Wo projection
// ============================================================
__global__ void __launch_bounds__(256, 2) gemm_mma(
    const __nv_bfloat16* __restrict__ Ah, const __nv_bfloat16* __restrict__ Al,
    const __nv_bfloat16* __restrict__ Bh, const __nv_bfloat16* __restrict__ Bl,
    float* __restrict__ C, int M, int N, int K)
{
    extern __shared__ char smem[];
    uint32_t sb = smem_u32(smem);
    int tid = threadIdx.x, lane = tid & 31, wid = tid >> 5;
    int m0 = blockIdx.y * 128, n0 = blockIdx.x * 128;
    int wm = (wid & 1) * 64, wn = (wid >> 1) * 32;

    float acc[4][4][4];
#pragma unroll
    for (int a = 0; a < 4; a++)
#pragma unroll
        for (int b = 0; b < 4; b++)
#pragma unroll
            for (int c = 0; c < 4; c++) acc[a][b][c] = 0.0f;

    gemm_core(sb, Ah, Al, Bh, Bl, m0, n0, K, tid, lane, wm, wn, acc);

    int g = lane >> 2, c2 = (lane & 3) * 2;
#pragma unroll
    for (int mt = 0; mt < 4; ++mt)
#pragma unroll
        for (int nt = 0; nt < 4; ++nt) {
            int row = m0 + wm + mt * 16 + g;
            int col = n0 + wn + nt * 8 + c2;
            *reinterpret_cast<float2*>(C + (size_t)row * N + col) =
                make_float2(acc[mt][nt][0], acc[mt][nt][1]);
            *reinterpret_cast<float2*>(C + (size_t)(row + 8) * N + col) =
                make_float2(acc[mt][nt][2], acc[mt][nt][3]);
        }
}

// ============================================================
// RoPE sin/cos table (fp64)
// ============================================================
__global__ void rope_table_kernel() {
    int i = blockIdx.x * blockDim.x + threadIdx.x;
    if (i >= TT * HALF_HD) return;
    int t = i / HALF_HD;
    int f = i % HALF_HD;
    double inv = exp(-((double)f / (double)HALF_HD) * log(10000.0));
    double ang = (double)t * inv;
    g_cos[i] = (float)cos(ang);
    g_sin[i] = (float)sin(ang);
}

// ============================================================
// prep_attn: fused RoPE+split for Q,K AND plain split for V
// (one launch; all DRAM-bound work together)
// ============================================================
#define NROPE (BB*TT*NH*HALF_HD)   // 4194304

__global__ void prep_attn(const float* __restrict__ q, const float* __restrict__ k,
                          const float* __restrict__ v,
                          __nv_bfloat16* __restrict__ qh, __nv_bfloat16* __restrict__ ql,
                          __nv_bfloat16* __restrict__ kh, __nv_bfloat16* __restrict__ kl,
                          __nv_bfloat16* __restrict__ vh, __nv_bfloat16* __restrict__ vl) {
    int i = blockIdx.x * blockDim.x + threadIdx.x;
    if (i < NROPE) {
        int f    = i & (HALF_HD - 1);
        int rest = i >> 5;
        int h    = rest & (NH - 1);
        int bt   = rest >> 4;
        int t    = bt & (TT - 1);
        int off  = bt * DM + h * HD + f;
        float c = g_cos[t * HALF_HD + f];
        float s = g_sin[t * HALF_HD + f];

        float q1 = q[off], q2 = q[off + HALF_HD];
        float qa = q1 * c - q2 * s;
        float qb = q2 * c + q1 * s;
        __nv_bfloat16 ha = __float2bfloat16(qa);
        __nv_bfloat16 hb = __float2bfloat16(qb);
        qh[off] = ha;  qh[off + HALF_HD] = hb;
        ql[off] = __float2bfloat16(qa - __bfloat162float(ha));
        ql[off + HALF_HD] = __float2bfloat16(qb - __bfloat162float(hb));

        float k1 = k[off], k2 = k[off + HALF_HD];
        float ka = k1 * c - k2 * s;
        float kb = k2 * c + k1 * s;
        ha = __float2bfloat16(ka);
        hb = __float2bfloat16(kb);
        kh[off] = ha;  kh[off + HALF_HD] = hb;
        kl[off] = __float2bfloat16(ka - __bfloat162float(ha));
        kl[off + HALF_HD] = __float2bfloat16(kb - __bfloat162float(hb));
    } else {
        int j = i - NROPE;
        if (j < X_N4) split_body(v, vh, vl, j);
    }
}

// ============================================================
// Tensor-core flash attention (causal, FA2-style, bf16x3)
// epilogue writes bf16 hi/lo aoh/aol (feeds Wo GEMM directly)
// ============================================================
#define FA_SMEM 98304
#define FQH 0
#define FQL 16384
#define FKH 0
#define FKL 8192
#define FVH 16384
#define FVL 24576

__global__ void __launch_bounds__(256) flash_mma(
    const __nv_bfloat16* __restrict__ qh, const __nv_bfloat16* __restrict__ ql,
    const __nv_bfloat16* __restrict__ kh, const __nv_bfloat16* __restrict__ kl,
    const __nv_bfloat16* __restrict__ vh, const __nv_bfloat16* __restrict__ vl,
    __nv_bfloat16* __restrict__ aoh, __nv_bfloat16* __restrict__ aol)
{
    extern __shared__ char smem[];
    uint32_t sb = smem_u32(smem);
    int tid = threadIdx.x, lane = tid & 31, w = tid >> 5;

    int qt = (int)gridDim.x - 1 - (int)blockIdx.x;
    int bh_ = blockIdx.y;
    int b = bh_ >> 4, h = bh_ & 15;
    size_t base = (size_t)b * TT * DM + h * HD;
    int q0 = qt * 128;

    const __nv_bfloat16* Qh = qh + base;
    const __nv_bfloat16* Ql = ql + base;
    const __nv_bfloat16* Kh = kh + base;
    const __nv_bfloat16* Kl = kl + base;
    const __nv_bfloat16* Vh = vh + base;
    const __nv_bfloat16* Vl = vl + base;

    for (int i = tid; i < 1024; i += 256) {
        int r = i >> 3, c = i & 7;
        size_t g = (size_t)(q0 + r) * DM + c * 8;
        cp16(sb + FQH + swz64(r, c), Qh + g);
        cp16(sb + FQL + swz64(r, c), Ql + g);
    }
    {
        uint32_t buf = sb + 32768;
        for (int i = tid; i < 512; i += 256) {
            int r = i >> 3, c = i & 7;
            size_t g = (size_t)r * DM + c * 8;
            uint32_t so = swz64(r, c);
            cp16(buf + FKH + so, Kh + g);
            cp16(buf + FKL + so, Kl + g);
            cp16(buf + FVH + so, Vh + g);
            cp16(buf + FVL + so, Vl + g);
        }
    }
    asm volatile("cp.async.commit_group;");

    const float NEG_INF = -__int_as_float(0x7f800000);
    float m0 = NEG_INF, m1 = NEG_INF, l0 = 0.0f, l1 = 0.0f;
    float o[8][4];
#pragma unroll
    for (int nt = 0; nt < 8; nt++)
#pragma unroll
        for (int c = 0; c < 4; c++) o[nt][c] = 0.0f;

    int nkt = 2 * qt + 2;
    int row0 = q0 + w * 16 + (lane >> 2);

    for (int kt = 0; kt < nkt; kt++) {
        uint32_t cur = sb + 32768u + (uint32_t)((kt & 1) * 32768);
        if (kt + 1 < nkt) {
            __syncthreads();
            uint32_t nb = sb + 32768u + (uint32_t)(((kt + 1) & 1) * 32768);
            int k0n = (kt + 1) * 64;
            for (int i = tid; i < 512; i += 256) {
                int r = i >> 3, c = i & 7;
                size_t g = (size_t)(k0n + r) * DM + c * 8;
                uint32_t so = swz64(r, c);
                cp16(nb + FKH + so, Kh + g);
                cp16(nb + FKL + so, Kl + g);
                cp16(nb + FVH + so, Vh + g);
                cp16(nb + FVL + so, Vl + g);
            }
            asm volatile("cp.async.commit_group;");
            asm volatile("cp.async.wait_group 1;");
        } else {
            asm volatile("cp.async.wait_group 0;");
        }
        __syncthreads();

        int k0 = kt * 64;

        float s[8][4];
#pragma unroll
        for (int nt = 0; nt < 8; nt++)
#pragma unroll
            for (int c = 0; c < 4; c++) s[nt][c] = 0.0f;

        int ra  = ((lane >> 3) & 1) * 8 + (lane & 7);
        int caf = (lane >> 4) & 1;
        int rb  = ((lane >> 4) & 1) * 8 + (lane & 7);
        int cbf = (lane >> 3) & 1;

#pragma unroll
        for (int ks = 0; ks < 4; ++ks) {
            uint32_t aH[4], aL[4];
            uint32_t qoff = swz64(w * 16 + ra, ks * 2 + caf);
            ldm4(aH, sb + FQH + qoff);
            ldm4(aL, sb + FQL + qoff);

            uint32_t bH[8][2], bL[8][2];
#pragma unroll
            for (int p = 0; p < 4; ++p) {
                uint32_t off = swz64(p * 16 + rb, ks * 2 + cbf);
                uint32_t t[4];
                ldm4(t, cur + FKH + off);
                bH[p*2][0] = t[0]; bH[p*2][1] = t[1];
                bH[p*2+1][0] = t[2]; bH[p*2+1][1] = t[3];
                ldm4(t, cur + FKL + off);
                bL[p*2][0] = t[0]; bL[p*2][1] = t[1];
                bL[p*2+1][0] = t[2]; bL[p*2+1][1] = t[3];
            }
#pragma unroll
            for (int nt = 0; nt < 8; ++nt) {
                mma16816(s[nt], aH, bH[nt]);
                mma16816(s[nt], aH, bL[nt]);
                mma16816(s[nt], aL, bH[nt]);
            }
        }

        bool needmask = (k0 + 63 > q0);
#pragma unroll
        for (int nt = 0; nt < 8; ++nt) {
#pragma unroll
            for (int c = 0; c < 4; ++c) {
                float v = s[nt][c] * 0.125f;
                if (needmask) {
                    int col = k0 + nt * 8 + (lane & 3) * 2 + (c & 1);
                    int rowg = row0 + ((c >> 1) << 3);
                    if (col > rowg) v = NEG_INF;
                }
                s[nt][c] = v;
            }
        }

        float mx0 = NEG_INF, mx1 = NEG_INF;
#pragma unroll
        for (int nt = 0; nt < 8; ++nt) {
            mx0 = fmaxf(mx0, fmaxf(s[nt][0], s[nt][1]));
            mx1 = fmaxf(mx1, fmaxf(s[nt][2], s[nt][3]));
        }
        mx0 = fmaxf(mx0, __shfl_xor_sync(0xffffffffu, mx0, 1));
        mx0 = fmaxf(mx0, __shfl_xor_sync(0xffffffffu, mx0, 2));
        mx1 = fmaxf(mx1, __shfl_xor_sync(0xffffffffu, mx1, 1));
        mx1 = fmaxf(mx1, __shfl_xor_sync(0xffffffffu, mx1, 2));

        float mn0 = fmaxf(m0, mx0), mn1 = fmaxf(m1, mx1);
        float al0 = __expf(m0 - mn0), al1 = __expf(m1 - mn1);
        if (m0 == NEG_INF && mn0 == NEG_INF) al0 = 1.0f;
        if (m1 == NEG_INF && mn1 == NEG_INF) al1 = 1.0f;
        m0 = mn0; m1 = mn1;

        float ls0 = 0.0f, ls1 = 0.0f;
#pragma unroll
        for (int nt = 0; nt < 8; ++nt) {
            float p0 = (s[nt][0] == NEG_INF) ? 0.0f : __expf(s[nt][0] - mn0);
            float p1 = (s[nt][1] == NEG_INF) ? 0.0f : __expf(s[nt][1] - mn0);
            float p2 = (s[nt][2] == NEG_INF) ? 0.0f : __expf(s[nt][2] - mn1);
            float p3 = (s[nt][3] == NEG_INF) ? 0.0f : __expf(s[nt][3] - mn1);
            s[nt][0] = p0; s[nt][1] = p1; s[nt][2] = p2; s[nt][3] = p3;
            ls0 += p0 + p1; ls1 += p2 + p3;
        }
        ls0 += __shfl_xor_sync(0xffffffffu, ls0, 1);
        ls0 += __shfl_xor_sync(0xffffffffu, ls0, 2);
        ls1 += __shfl_xor_sync(0xffffffffu, ls1, 1);
        ls1 += __shfl_xor_sync(0xffffffffu, ls1, 2);
        l0 = l0 * al0 + ls0;
        l1 = l1 * al1 + ls1;

#pragma unroll
        for (int nt = 0; nt < 8; ++nt) {
            o[nt][0] *= al0; o[nt][1] *= al0;
            o[nt][2] *= al1; o[nt][3] *= al1;
        }

#pragma unroll
        for (int ks = 0; ks < 4; ++ks) {
            uint32_t pH[4], pL[4];
            splitpack(s[2*ks][0],   s[2*ks][1],   pH[0], pL[0]);
            splitpack(s[2*ks][2],   s[2*ks][3],   pH[1], pL[1]);
            splitpack(s[2*ks+1][0], s[2*ks+1][1], pH[2], pL[2]);
            splitpack(s[2*ks+1][2], s[2*ks+1][3], pH[3], pL[3]);

            int mm = lane >> 3, la = lane & 7;
            int vrow = ks * 16 + (mm & 1) * 8 + la;
#pragma unroll
            for (int ntp = 0; ntp < 4; ++ntp) {
                int vchunk = ntp * 2 + (mm >> 1);
                uint32_t off = swz64(vrow, vchunk);
                uint32_t tH[4], tL[4];
                ldm4t(tH, cur + FVH + off);
                ldm4t(tL, cur + FVL + off);
                uint32_t b0H[2] = {tH[0], tH[1]}, b1H[2] = {tH[2], tH[3]};
                uint32_t b0L[2] = {tL[0], tL[1]}, b1L[2] = {tL[2], tL[3]};
                mma16816(o[2*ntp],   pH, b0H);
                mma16816(o[2*ntp],   pH, b0L);
                mma16816(o[2*ntp],   pL, b0H);
                mma16816(o[2*ntp+1], pH, b1H);
                mma16816(o[2*ntp+1], pH, b1L);
                mma16816(o[2*ntp+1], pL, b1H);
            }
        }
    }

    // ---- epilogue: write bf16 hi/lo directly (feeds Wo GEMM) ----
    float inv0 = 1.0f / l0, inv1 = 1.0f / l1;
    __nv_bfloat16* Oh = aoh + base;
    __nv_bfloat16* Ol = aol + base;
    int c2 = (lane & 3) * 2;
#pragma unroll
    for (int nt = 0; nt < 8; ++nt) {
        uint32_t hh, ll;
        splitpack(o[nt][0] * inv0, o[nt][1] * inv0, hh, ll);
        *reinterpret_cast<uint32_t*>(Oh + (size_t)row0 * DM + nt * 8 + c2) = hh;
        *reinterpret_cast<uint32_t*>(Ol + (size_t)row0 * DM + nt * 8 + c2) = ll;
        splitpack(o[nt][2] * inv1, o[nt][3] * inv1, hh, ll);
        *reinterpret_cast<uint32_t*>(Oh + (size_t)(row0 + 8) * DM + nt * 8 + c2) = hh;
        *reinterpret_cast<uint32_t*>(Ol + (size_t)(row0 + 8) * DM + nt * 8 + c2) = ll;
    }
}

// ============================================================
// launch — gemm_qkv at our #4 so ncu (-s 5, harness +2) profiles it
// ============================================================
extern "C" void kernel_launch(void* const* d_in, const int* in_sizes, int n_in,
                              void* d_out, int out_size) {
    const float* x  = (const float*)d_in[0];
    const float* Wq = (const float*)d_in[1];
    const float* Wk = (const float*)d_in[2];
    const float* Wv = (const float*)d_in[3];
    const float* Wo = (const float*)d_in[4];
    float* out = (float*)d_out;

    float *q, *k, *v;
    cudaGetSymbolAddress((void**)&q,  g_q);
    cudaGetSymbolAddress((void**)&k,  g_k);
    cudaGetSymbolAddress((void**)&v,  g_v);

    __nv_bfloat16 *xh, *xl, *aoh, *aol, *wh, *wl;
    __nv_bfloat16 *qh, *ql, *kh, *kl, *vh, *vl;
    cudaGetSymbolAddress((void**)&xh,  g_xh);
    cudaGetSymbolAddress((void**)&xl,  g_xl);
    cudaGetSymbolAddress((void**)&aoh, g_aoh);
    cudaGetSymbolAddress((void**)&aol, g_aol);
    cudaGetSymbolAddress((void**)&wh,  g_wh);
    cudaGetSymbolAddress((void**)&wl,  g_wl);
    cudaGetSymbolAddress((void**)&qh,  g_qh);
    cudaGetSymbolAddress((void**)&ql,  g_ql);
    cudaGetSymbolAddress((void**)&kh,  g_kh);
    cudaGetSymbolAddress((void**)&kl,  g_kl);
    cudaGetSymbolAddress((void**)&vh,  g_vh);
    cudaGetSymbolAddress((void**)&vl,  g_vl);

    cudaFuncSetAttribute(gemm_qkv,  cudaFuncAttributeMaxDynamicSharedMemorySize, GM_SMEM);
    cudaFuncSetAttribute(gemm_mma,  cudaFuncAttributeMaxDynamicSharedMemorySize, GM_SMEM);
    cudaFuncSetAttribute(flash_mma, cudaFuncAttributeMaxDynamicSharedMemorySize, FA_SMEM);

    // #1
    rope_table_kernel<<<(TT * HALF_HD + 255) / 256, 256>>>();
    // #2 — fused x + 4 weight splits
    split_all<<<(X_N4 + 4 * W_N4 + 255) / 256, 256>>>(
        x, Wq, Wk, Wv, Wo, xh, xl, wh, wl);
    // #3 — dummy (positions gemm_qkv at #4 for ncu)
    dummy_kernel<<<1, 32>>>();
    // #4 — fused QKV projections (profiled by ncu)
    gemm_qkv<<<dim3(DM / 128, MROWS / 128, 3), 256, GM_SMEM>>>(
        xh, xl, wh, wl, q, k, v);
    // #5 — fused rope-split (q,k) + split (v)
    prep_attn<<<(NROPE + X_N4 + 255) / 256, 256>>>(
        q, k, v, qh, ql, kh, kl, vh, vl);
    // #6 — flash attention, writes bf16 hi/lo directly
    flash_mma<<<dim3(TT / 128, BB * NH), 256, FA_SMEM>>>(qh, ql, kh, kl, vh, vl, aoh, aol);
    // #7 — output projection
    gemm_mma<<<dim3(DM / 128, MROWS / 128), 256, GM_SMEM>>>(
        aoh, aol, wh + 3 * (size_t)DM * DM, wl + 3 * (size_t)DM * DM, out, MROWS, DM, DM);
}